// round 1
// baseline (speedup 1.0000x reference)
#include <cuda_runtime.h>
#include <math.h>
#include <stdint.h>

#define B_    8
#define T_    12
#define N_    1536
#define H_    64
#define TH_   768
#define HID2_ 128
#define TOUT_ 12
#define M_    (B_*N_)          // 12288
#define DELTA_   0.5f
#define ALPHA_   0.3f
#define KHOPS_   3.0f
#define KL_EPS_  1e-10f
#define BN_EPS_  1e-5f
#define DEG_MIN_ 1e-6f

// ---------------- device scratch ----------------
__device__ float g_p [M_*T_];
__device__ float g_lp[M_*T_];
__device__ float g_s [M_];
__device__ float g_deg[M_];
__device__ float g_ind[M_];
__device__ float g_af[M_*T_];
__device__ float g_ab[M_*T_];
__device__ float g_gg[M_*T_];
__device__ float g_z [M_*TH_];
__device__ float g_h1[(size_t)M_*HID2_];
__device__ float g_zp[(size_t)M_*H_];
__device__ float g_h2[(size_t)M_*HID2_];
__device__ float g_e [(size_t)M_*H_];
__device__ float g_h3[(size_t)M_*HID2_];
__device__ float g_h4[(size_t)M_*HID2_];

// ---------------- K0: zero accumulators ----------------
__global__ void k_zero() {
    int i = blockIdx.x * 128 + threadIdx.x;   // grid covers M_*T_
    if (i < M_) { g_deg[i] = 0.f; g_ind[i] = 0.f; }
    if (i < M_*T_) { g_af[i] = 0.f; g_ab[i] = 0.f; }
}

// ---------------- K1: per-node softmax over T, logp, s ----------------
__global__ void k_softmax(const float* __restrict__ x) {
    int bn = blockIdx.x * 128 + threadIdx.x;
    if (bn >= M_) return;
    int b = bn / N_, n = bn % N_;
    float v[T_];
    float mx = -1e30f;
#pragma unroll
    for (int t = 0; t < T_; t++) {
        v[t] = x[((size_t)(b*T_ + t))*N_ + n];
        mx = fmaxf(mx, v[t]);
    }
    float sum = 0.f;
#pragma unroll
    for (int t = 0; t < T_; t++) { v[t] = expf(v[t] - mx); sum += v[t]; }
    float inv = 1.f / sum;
    float s = 0.f;
    size_t base = (size_t)bn * T_;
#pragma unroll
    for (int t = 0; t < T_; t++) {
        float p  = v[t] * inv;
        float lp = logf(p + KL_EPS_);
        g_p [base + t] = p;
        g_lp[base + t] = lp;
        s = fmaf(p, lp, s);
    }
    g_s[bn] = s;
}

// ---------------- helper: 12-float smem load via float4 ----------------
__device__ __forceinline__ void load12(float* d, const float* s) {
    float4 a = ((const float4*)s)[0];
    float4 b = ((const float4*)s)[1];
    float4 c = ((const float4*)s)[2];
    d[0]=a.x; d[1]=a.y; d[2]=a.z;  d[3]=a.w;
    d[4]=b.x; d[5]=b.y; d[6]=b.z;  d[7]=b.w;
    d[8]=c.x; d[9]=c.y; d[10]=c.z; d[11]=c.w;
}

// ---------------- K2: graph threshold + masked aggregation ----------------
// grid: (N/128 i-tiles, N/128 j-tiles, B), 128 threads, thread owns row i.
__global__ void __launch_bounds__(128) k_graph(const float* __restrict__ x) {
    __shared__ float psh[128*T_];
    __shared__ float lsh[128*T_];
    __shared__ float xsh[128*T_];
    __shared__ float ssh[128];

    const int tid = threadIdx.x;
    const int b   = blockIdx.z;
    const int i   = blockIdx.x * 128 + tid;
    const int j0  = blockIdx.y * 128;
    const int bN  = b * N_;

    {
        size_t base = (size_t)(bN + j0) * T_;
        for (int idx = tid; idx < 128*T_; idx += 128) {
            psh[idx] = g_p [base + idx];
            lsh[idx] = g_lp[base + idx];
        }
#pragma unroll
        for (int t = 0; t < T_; t++)
            xsh[tid*T_ + t] = x[((size_t)(b*T_ + t))*N_ + j0 + tid];
        ssh[tid] = g_s[bN + j0 + tid];
    }

    float pi[T_], li[T_];
    load12(pi, &g_p [(size_t)(bN + i)*T_]);
    load12(li, &g_lp[(size_t)(bN + i)*T_]);
    const float si = g_s[bN + i];

    float accf[T_], accb[T_];
#pragma unroll
    for (int t = 0; t < T_; t++) { accf[t] = 0.f; accb[t] = 0.f; }
    float deg = 0.f, ind = 0.f;

    __syncthreads();

    for (int jj = 0; jj < 128; jj++) {
        float pj[T_], lj[T_], xj[T_];
        load12(pj, &psh[jj*T_]);
        load12(lj, &lsh[jj*T_]);
        float d1 = 0.f, d2 = 0.f;
#pragma unroll
        for (int t = 0; t < T_; t++) {
            d1 = fmaf(pi[t], lj[t], d1);   // M[i,j]
            d2 = fmaf(pj[t], li[t], d2);   // M[j,i]
        }
        float mf = ((si - d1)      < DELTA_) ? 1.f : 0.f;  // A[i,j]
        float mb = ((ssh[jj] - d2) < DELTA_) ? 1.f : 0.f;  // A[j,i]
        deg += mf; ind += mb;
        load12(xj, &xsh[jj*T_]);
#pragma unroll
        for (int t = 0; t < T_; t++) {
            accf[t] = fmaf(mf, xj[t], accf[t]);
            accb[t] = fmaf(mb, xj[t], accb[t]);
        }
    }

    atomicAdd(&g_deg[bN + i], deg);
    atomicAdd(&g_ind[bN + i], ind);
    size_t obase = (size_t)(bN + i) * T_;
#pragma unroll
    for (int t = 0; t < T_; t++) {
        atomicAdd(&g_af[obase + t], accf[t]);
        atomicAdd(&g_ab[obase + t], accb[t]);
    }
}

// ---------------- K2b: finalize message g = K*(a*yf + (1-a)*yb) ----------------
__global__ void k_gfin() {
    int idx = blockIdx.x * 128 + threadIdx.x;  // < M_*T_
    if (idx >= M_*T_) return;
    int row = idx / T_;
    float df = fmaxf(g_deg[row], DEG_MIN_);
    float db = fmaxf(g_ind[row], DEG_MIN_);
    g_gg[idx] = KHOPS_ * (ALPHA_ * g_af[idx] / df + (1.f - ALPHA_) * g_ab[idx] / db);
}

// ---------------- K3: build z = relu(x*W1 + g*W2), (M, 768) ----------------
__global__ void k_buildz(const float* __restrict__ x,
                         const float* __restrict__ W1,
                         const float* __restrict__ W2) {
    int idx = blockIdx.x * 256 + threadIdx.x;   // < M_*TH_
    if (idx >= M_*TH_) return;
    int row = idx / TH_;
    int c   = idx % TH_;
    int t   = c >> 6;      // /64
    int h   = c & 63;
    int b = row / N_, n = row % N_;
    float xv = x[((size_t)(b*T_ + t))*N_ + n];
    float gg = g_gg[row*T_ + t];
    float v  = fmaf(xv, W1[h], gg * W2[h]);
    g_z[idx] = fmaxf(v, 0.f);
}

// ---------------- generic fp32 GEMM: C(M,BN) = A(M,K) @ Bw(K,BN) + epilogue ----------------
template<int BN, int TN, bool RELU, bool HASBIAS, bool HASAUX, bool DOBN>
__global__ void __launch_bounds__(256) k_gemm(
    const float* __restrict__ A, const float* __restrict__ Bw,
    float* __restrict__ C, int K,
    const float* __restrict__ bias,
    const float* __restrict__ aux,
    const float* __restrict__ bng, const float* __restrict__ bnb,
    const float* __restrict__ bnm, const float* __restrict__ bnv)
{
    constexpr int BM = 64, BK = 8, TM = 4;
    constexpr int TX = BN / TN;          // 16
    __shared__ float As[BK][BM];
    __shared__ float Bs[BK][BN];

    const int tid = threadIdx.x;
    const int tx = tid % TX;
    const int ty = tid / TX;             // 0..15
    const int m0 = blockIdx.x * BM;

    float acc[TM][TN];
#pragma unroll
    for (int i = 0; i < TM; i++)
#pragma unroll
        for (int j = 0; j < TN; j++) acc[i][j] = 0.f;

    const int a_m = tid >> 2;            // 0..63
    const int a_k = (tid & 3) * 2;       // 0,2,4,6
    const int b_k = tid >> 5;            // 0..7
    const int b_n = (tid & 31) * (BN / 32);

    for (int k0 = 0; k0 < K; k0 += BK) {
        float2 av = *(const float2*)&A[(size_t)(m0 + a_m)*K + k0 + a_k];
        As[a_k    ][a_m] = av.x;
        As[a_k + 1][a_m] = av.y;
        if (BN == 128) {
            float4 bv = *(const float4*)&Bw[(size_t)(k0 + b_k)*BN + b_n];
            *(float4*)&Bs[b_k][b_n] = bv;
        } else {
            float2 bv = *(const float2*)&Bw[(size_t)(k0 + b_k)*BN + b_n];
            *(float2*)&Bs[b_k][b_n] = bv;
        }
        __syncthreads();
#pragma unroll
        for (int kk = 0; kk < BK; kk++) {
            float rm[TM], rn[TN];
#pragma unroll
            for (int i = 0; i < TM; i++) rm[i] = As[kk][ty*TM + i];
#pragma unroll
            for (int j = 0; j < TN; j++) rn[j] = Bs[kk][tx*TN + j];
#pragma unroll
            for (int i = 0; i < TM; i++)
#pragma unroll
                for (int j = 0; j < TN; j++)
                    acc[i][j] = fmaf(rm[i], rn[j], acc[i][j]);
        }
        __syncthreads();
    }

#pragma unroll
    for (int i = 0; i < TM; i++) {
        int m = m0 + ty*TM + i;
#pragma unroll
        for (int j = 0; j < TN; j++) {
            int n = tx*TN + j;
            float c = acc[i][j];
            if (HASBIAS) c += bias[n];
            if (HASAUX)  c += aux[(size_t)m*BN + n];
            if (DOBN)    c = (c - bnm[n]) * rsqrtf(bnv[n] + BN_EPS_) * bng[n] + bnb[n];
            if (RELU)    c = fmaxf(c, 0.f);
            C[(size_t)m*BN + n] = c;
        }
    }
}

// ---------------- K7: final stage, N=12, fused dual-GEMM + BN + transpose ----------------
__global__ void __launch_bounds__(128) k_final(
    const float* __restrict__ w3,  const float* __restrict__ b3,
    const float* __restrict__ pj,
    const float* __restrict__ bng, const float* __restrict__ bnb,
    const float* __restrict__ bnm, const float* __restrict__ bnv,
    float* __restrict__ out)
{
    __shared__ float w3s[HID2_*TOUT_];
    __shared__ float pjs[H_*TOUT_];
    const int tid = threadIdx.x;
    for (int idx = tid; idx < HID2_*TOUT_; idx += 128) w3s[idx] = w3[idx];
    for (int idx = tid; idx < H_*TOUT_;    idx += 128) pjs[idx] = pj[idx];
    __syncthreads();

    const int row = blockIdx.x * 128 + tid;
    float acc[TOUT_];
#pragma unroll
    for (int o = 0; o < TOUT_; o++) acc[o] = b3[o];

    const float4* hr = (const float4*)&g_h4[(size_t)row * HID2_];
#pragma unroll 4
    for (int k4 = 0; k4 < HID2_/4; k4++) {
        float4 hv = __ldg(&hr[k4]);
        float h[4] = {hv.x, hv.y, hv.z, hv.w};
#pragma unroll
        for (int q = 0; q < 4; q++) {
            int k = k4*4 + q;
#pragma unroll
            for (int o = 0; o < TOUT_; o++)
                acc[o] = fmaf(h[q], w3s[k*TOUT_ + o], acc[o]);
        }
    }
    const float4* er = (const float4*)&g_e[(size_t)row * H_];
#pragma unroll 4
    for (int k4 = 0; k4 < H_/4; k4++) {
        float4 ev = __ldg(&er[k4]);
        float e4[4] = {ev.x, ev.y, ev.z, ev.w};
#pragma unroll
        for (int q = 0; q < 4; q++) {
            int k = k4*4 + q;
#pragma unroll
            for (int o = 0; o < TOUT_; o++)
                acc[o] = fmaf(e4[q], pjs[k*TOUT_ + o], acc[o]);
        }
    }

    const int b = row / N_, n = row % N_;
#pragma unroll
    for (int o = 0; o < TOUT_; o++) {
        float c = (acc[o] - bnm[o]) * rsqrtf(bnv[o] + BN_EPS_) * bng[o] + bnb[o];
        out[((size_t)(b*TOUT_ + o))*N_ + n] = c;
    }
}

// ---------------- host launch ----------------
extern "C" void kernel_launch(void* const* d_in, const int* in_sizes, int n_in,
                              void* d_out, int out_size)
{
    const float* x        = (const float*)d_in[0];
    const float* W1       = (const float*)d_in[1];
    const float* W2       = (const float*)d_in[2];
    const float* enc_w1   = (const float*)d_in[3];
    const float* enc_b1   = (const float*)d_in[4];
    const float* enc_w2   = (const float*)d_in[5];
    const float* enc_b2   = (const float*)d_in[6];
    const float* enc_w3   = (const float*)d_in[7];
    const float* enc_b3   = (const float*)d_in[8];
    const float* enc_proj = (const float*)d_in[9];
    const float* enc_bn_g = (const float*)d_in[10];
    const float* enc_bn_b = (const float*)d_in[11];
    const float* enc_bn_m = (const float*)d_in[12];
    const float* enc_bn_v = (const float*)d_in[13];
    const float* dec_w1   = (const float*)d_in[14];
    const float* dec_b1   = (const float*)d_in[15];
    const float* dec_w2   = (const float*)d_in[16];
    const float* dec_b2   = (const float*)d_in[17];
    const float* dec_w3   = (const float*)d_in[18];
    const float* dec_b3   = (const float*)d_in[19];
    const float* dec_proj = (const float*)d_in[20];
    const float* dec_bn_g = (const float*)d_in[21];
    const float* dec_bn_b = (const float*)d_in[22];
    const float* dec_bn_m = (const float*)d_in[23];
    const float* dec_bn_v = (const float*)d_in[24];
    float* out = (float*)d_out;

    // device scratch addresses (symbol lookups; no allocation)
    void *pz, *ph1, *pzp, *ph2, *pe, *ph3, *ph4;
    cudaGetSymbolAddress(&pz,  g_z);
    cudaGetSymbolAddress(&ph1, g_h1);
    cudaGetSymbolAddress(&pzp, g_zp);
    cudaGetSymbolAddress(&ph2, g_h2);
    cudaGetSymbolAddress(&pe,  g_e);
    cudaGetSymbolAddress(&ph3, g_h3);
    cudaGetSymbolAddress(&ph4, g_h4);
    float* Z  = (float*)pz;
    float* H1 = (float*)ph1;
    float* ZP = (float*)pzp;
    float* H2 = (float*)ph2;
    float* E  = (float*)pe;
    float* H3 = (float*)ph3;
    float* H4 = (float*)ph4;

    k_zero   <<<(M_*T_)/128, 128>>>();
    k_softmax<<<M_/128, 128>>>(x);
    k_graph  <<<dim3(N_/128, N_/128, B_), 128>>>(x);
    k_gfin   <<<(M_*T_)/128, 128>>>();
    k_buildz <<<(M_*TH_)/256, 256>>>(x, W1, W2);

    const int GB = M_ / 64;  // 192 blocks

    // h1 = relu(z @ enc_w1 + b1)   (K=768, N=128)
    k_gemm<128,8,true ,true ,false,false><<<GB,256>>>(Z,  enc_w1,   H1, TH_,
        enc_b1, nullptr, nullptr, nullptr, nullptr, nullptr);
    // zp = z @ enc_proj            (K=768, N=64)
    k_gemm< 64,4,false,false,false,false><<<GB,256>>>(Z,  enc_proj, ZP, TH_,
        nullptr, nullptr, nullptr, nullptr, nullptr, nullptr);
    // h2 = relu(h1 @ enc_w2 + b2)  (K=128, N=128)
    k_gemm<128,8,true ,true ,false,false><<<GB,256>>>(H1, enc_w2,   H2, HID2_,
        enc_b2, nullptr, nullptr, nullptr, nullptr, nullptr);
    // e = BN(h2 @ enc_w3 + b3 + zp) (K=128, N=64)
    k_gemm< 64,4,false,true ,true ,true ><<<GB,256>>>(H2, enc_w3,   E,  HID2_,
        enc_b3, ZP, enc_bn_g, enc_bn_b, enc_bn_m, enc_bn_v);
    // h3 = relu(e @ dec_w1 + db1)  (K=64, N=128)
    k_gemm<128,8,true ,true ,false,false><<<GB,256>>>(E,  dec_w1,   H3, H_,
        dec_b1, nullptr, nullptr, nullptr, nullptr, nullptr);
    // h4 = relu(h3 @ dec_w2 + db2) (K=128, N=128)
    k_gemm<128,8,true ,true ,false,false><<<GB,256>>>(H3, dec_w2,   H4, HID2_,
        dec_b2, nullptr, nullptr, nullptr, nullptr, nullptr);

    // out = transpose(BN(h4 @ dec_w3 + db3 + e @ dec_proj))
    k_final<<<M_/128, 128>>>(dec_w3, dec_b3, dec_proj,
                             dec_bn_g, dec_bn_b, dec_bn_m, dec_bn_v, out);
}

// round 2
// speedup vs baseline: 1.6208x; 1.6208x over previous
#include <cuda_runtime.h>
#include <math.h>

#define B_    8
#define T_    12
#define N_    1536
#define H_    64
#define TH_   768
#define HID2_ 128
#define TOUT_ 12
#define M_    (B_*N_)          // 12288
#define DELTA_   0.5f
#define ALPHA_   0.3f
#define KHOPS_   3.0f
#define KL_EPS_  1e-10f
#define BN_EPS_  1e-5f
#define DEG_MIN_ 1e-6f

typedef unsigned long long u64;

// ---------------- packed fp32x2 helpers (sm_103a FFMA2) ----------------
__device__ __forceinline__ u64 fma2(u64 a, u64 b, u64 c) {
    u64 d;
    asm("fma.rn.f32x2 %0, %1, %2, %3;" : "=l"(d) : "l"(a), "l"(b), "l"(c));
    return d;
}
__device__ __forceinline__ u64 pack2(float x, float y) {
    u64 d;
    asm("mov.b64 %0, {%1, %2};" : "=l"(d) : "f"(x), "f"(y));
    return d;
}
__device__ __forceinline__ float2 unpack2(u64 v) {
    float2 r;
    asm("mov.b64 {%0, %1}, %2;" : "=f"(r.x), "=f"(r.y) : "l"(v));
    return r;
}

// ---------------- device scratch ----------------
__device__ __align__(16) float g_p [M_*T_];
__device__ __align__(16) float g_lp[M_*T_];
__device__ float g_s  [M_];
__device__ float g_deg[M_];
__device__ float g_ind[M_];
__device__ __align__(16) float g_af[M_*T_];
__device__ __align__(16) float g_ab[M_*T_];
__device__ __align__(16) float g_gg[M_*T_];
__device__ __align__(16) float g_z [(size_t)M_*TH_];
__device__ __align__(16) float g_h1[(size_t)M_*HID2_];
__device__ __align__(16) float g_zp[(size_t)M_*H_];
__device__ __align__(16) float g_h2[(size_t)M_*HID2_];
__device__ __align__(16) float g_e [(size_t)M_*H_];
__device__ __align__(16) float g_h3[(size_t)M_*HID2_];
__device__ __align__(16) float g_h4[(size_t)M_*HID2_];

// ---------------- K1: per-node softmax over T, logp, s; also zeros accumulators ----------------
__global__ void k_softmax(const float* __restrict__ x) {
    int bn = blockIdx.x * 128 + threadIdx.x;
    if (bn >= M_) return;
    int b = bn / N_, n = bn % N_;
    float v[T_];
    float mx = -1e30f;
#pragma unroll
    for (int t = 0; t < T_; t++) {
        v[t] = x[((size_t)(b*T_ + t))*N_ + n];
        mx = fmaxf(mx, v[t]);
    }
    float sum = 0.f;
#pragma unroll
    for (int t = 0; t < T_; t++) { v[t] = expf(v[t] - mx); sum += v[t]; }
    float inv = 1.f / sum;
    float s = 0.f;
    size_t base = (size_t)bn * T_;
#pragma unroll
    for (int t = 0; t < T_; t++) {
        float p  = v[t] * inv;
        float lp = logf(p + KL_EPS_);
        g_p [base + t] = p;
        g_lp[base + t] = lp;
        g_af[base + t] = 0.f;
        g_ab[base + t] = 0.f;
        s = fmaf(p, lp, s);
    }
    g_s[bn] = s;
    g_deg[bn] = 0.f;
    g_ind[bn] = 0.f;
}

// ---------------- K2: graph threshold + masked aggregation (f32x2 packed over t) ----------------
#define JC 256
__global__ void __launch_bounds__(128) k_graph(const float* __restrict__ x) {
    __shared__ __align__(16) float psh[JC*T_];
    __shared__ __align__(16) float lsh[JC*T_];
    __shared__ __align__(16) float xsh[JC*T_];
    __shared__ float ssh[JC];

    const int tid = threadIdx.x;
    const int b   = blockIdx.z;
    const int i   = blockIdx.x * 128 + tid;
    const int j0  = blockIdx.y * JC;
    const int bN  = b * N_;

    {
        size_t base = (size_t)(bN + j0) * T_;
        const float4* sp = (const float4*)(g_p  + base);
        const float4* sl = (const float4*)(g_lp + base);
#pragma unroll
        for (int q = 0; q < (JC*T_/4)/128; q++) {
            int idx = q*128 + tid;
            ((float4*)psh)[idx] = sp[idx];
            ((float4*)lsh)[idx] = sl[idx];
        }
#pragma unroll
        for (int t = 0; t < T_; t++) {
            xsh[tid*T_ + t]        = x[((size_t)(b*T_ + t))*N_ + j0 + tid];
            xsh[(tid+128)*T_ + t]  = x[((size_t)(b*T_ + t))*N_ + j0 + tid + 128];
        }
        ssh[tid]       = g_s[bN + j0 + tid];
        ssh[tid + 128] = g_s[bN + j0 + tid + 128];
    }

    u64 pi2[6], li2[6];
    {
        const ulonglong2* pp = (const ulonglong2*)(g_p  + (size_t)(bN + i)*T_);
        const ulonglong2* lp = (const ulonglong2*)(g_lp + (size_t)(bN + i)*T_);
#pragma unroll
        for (int q = 0; q < 3; q++) {
            ulonglong2 a = pp[q]; pi2[2*q] = a.x; pi2[2*q+1] = a.y;
            ulonglong2 c = lp[q]; li2[2*q] = c.x; li2[2*q+1] = c.y;
        }
    }
    const float si = g_s[bN + i];

    u64 accf2[6], accb2[6];
#pragma unroll
    for (int t = 0; t < 6; t++) { accf2[t] = 0ull; accb2[t] = 0ull; }
    float deg = 0.f, ind = 0.f;

    __syncthreads();

    for (int jj = 0; jj < JC; jj++) {
        const u64* pj2 = (const u64*)(psh + jj*T_);
        const u64* lj2 = (const u64*)(lsh + jj*T_);
        u64 d1 = 0ull, d2 = 0ull;
#pragma unroll
        for (int t = 0; t < 6; t++) {
            d1 = fma2(pi2[t], lj2[t], d1);   // p_i . logp_j
            d2 = fma2(pj2[t], li2[t], d2);   // p_j . logp_i
        }
        float2 r1 = unpack2(d1);
        float2 r2 = unpack2(d2);
        float d1s = r1.x + r1.y;
        float d2s = r2.x + r2.y;
        float mf = ((si - d1s)      < DELTA_) ? 1.f : 0.f;  // A[i,j]
        float mb = ((ssh[jj] - d2s) < DELTA_) ? 1.f : 0.f;  // A[j,i]
        deg += mf; ind += mb;
        u64 mf2 = pack2(mf, mf);
        u64 mb2 = pack2(mb, mb);
        const u64* xj2 = (const u64*)(xsh + jj*T_);
#pragma unroll
        for (int t = 0; t < 6; t++) {
            u64 xv = xj2[t];
            accf2[t] = fma2(mf2, xv, accf2[t]);
            accb2[t] = fma2(mb2, xv, accb2[t]);
        }
    }

    atomicAdd(&g_deg[bN + i], deg);
    atomicAdd(&g_ind[bN + i], ind);
    size_t obase = (size_t)(bN + i) * T_;
#pragma unroll
    for (int t = 0; t < 6; t++) {
        float2 f = unpack2(accf2[t]);
        float2 g = unpack2(accb2[t]);
        atomicAdd(&g_af[obase + 2*t    ], f.x);
        atomicAdd(&g_af[obase + 2*t + 1], f.y);
        atomicAdd(&g_ab[obase + 2*t    ], g.x);
        atomicAdd(&g_ab[obase + 2*t + 1], g.y);
    }
}

// ---------------- K2b: finalize message (per-row reciprocal) ----------------
__global__ void k_gfin() {
    int row = blockIdx.x * 128 + threadIdx.x;
    if (row >= M_) return;
    float rf = (KHOPS_ * ALPHA_)        * __frcp_rn(fmaxf(g_deg[row], DEG_MIN_));
    float rb = (KHOPS_ * (1.f-ALPHA_))  * __frcp_rn(fmaxf(g_ind[row], DEG_MIN_));
    size_t base = (size_t)row * T_;
#pragma unroll
    for (int t = 0; t < T_; t++)
        g_gg[base + t] = rf * g_af[base + t] + rb * g_ab[base + t];
}

// ---------------- K3: build z = relu(x*W1 + g*W2), (M, 768) ----------------
__global__ void k_buildz(const float* __restrict__ x,
                         const float* __restrict__ W1,
                         const float* __restrict__ W2) {
    int idx = blockIdx.x * 256 + threadIdx.x;
    if (idx >= M_*TH_) return;
    int row = idx / TH_;
    int c   = idx % TH_;
    int t   = c >> 6;
    int h   = c & 63;
    int b = row / N_, n = row % N_;
    float xv = x[((size_t)(b*T_ + t))*N_ + n];
    float gg = g_gg[row*T_ + t];
    float v  = fmaf(xv, W1[h], gg * W2[h]);
    g_z[idx] = fmaxf(v, 0.f);
}

// ---------------- f32x2 GEMM body: C(M,BN) = A(M,K) @ Bw(K,BN) + epilogue ----------------
// 128 threads. BN=128: TXC=16, TM=8. BN=64: TXC=8, TM=4. BM=64, BK=16.
// A duplicated (v,v) in smem -> broadcast LDS.128 yields packed pairs.
// B natural; per-thread TN=8 as two half-groups of 4 cols (conflict-free LDS.128).
template<int BN, bool RELU, bool HASBIAS, bool HASAUX, bool DOBN>
__device__ __forceinline__ void gemm_body(
    const float* __restrict__ A, const float* __restrict__ Bw,
    float* __restrict__ C, int K, int mblk,
    const float* __restrict__ bias, const float* __restrict__ aux,
    const float* __restrict__ bng, const float* __restrict__ bnb,
    const float* __restrict__ bnm, const float* __restrict__ bnv,
    char* smem)
{
    constexpr int BK = 16, BM = 64;
    constexpr int TXC = (BN == 128) ? 16 : 8;
    constexpr int TM  = (BN == 128) ? 8  : 4;
    constexpr int PITCH = BM + 2;   // float2 units; kills fill STS conflicts, keeps 16B align
    float2* Asd = (float2*)smem;                                  // BK*PITCH float2
    float*  Bs  = (float*)(smem + BK*PITCH*sizeof(float2));       // BK*BN floats

    const int tid  = threadIdx.x;
    const int lane = tid & 31, warp = tid >> 5;
    const int tx = lane % TXC;
    const int ty = warp * (32/TXC) + lane / TXC;
    const int m0 = mblk * BM;
    const int c0 = tx * 4;
    const int c1 = BN/2 + tx * 4;

    u64 acc[TM][4];
#pragma unroll
    for (int i = 0; i < TM; i++)
#pragma unroll
        for (int j = 0; j < 4; j++) acc[i][j] = 0ull;

    for (int k0 = 0; k0 < K; k0 += BK) {
        // fill Asd (duplicated): BK*BM = 1024 values, 8 per thread, k-fast coalesced
#pragma unroll
        for (int q = 0; q < 8; q++) {
            int idx = q*128 + tid;
            int k = idx & (BK-1);
            int m = idx >> 4;
            float v = A[(size_t)(m0 + m)*K + k0 + k];
            Asd[k*PITCH + m] = make_float2(v, v);
        }
        // fill Bs: BK*BN floats, float4 per thread
#pragma unroll
        for (int q = 0; q < BN/32; q++) {
            int idx4 = q*128 + tid;
            int k  = idx4 / (BN/4);
            int n4 = (idx4 % (BN/4)) * 4;
            *(float4*)&Bs[k*BN + n4] = *(const float4*)&Bw[(size_t)(k0 + k)*BN + n4];
        }
        __syncthreads();
#pragma unroll
        for (int kk = 0; kk < BK; kk++) {
            u64 rm[TM];
#pragma unroll
            for (int i2 = 0; i2 < TM/2; i2++) {
                ulonglong2 v = *(const ulonglong2*)&Asd[kk*PITCH + ty*TM + 2*i2];
                rm[2*i2] = v.x; rm[2*i2+1] = v.y;
            }
            ulonglong2 bl = *(const ulonglong2*)&Bs[kk*BN + c0];
            ulonglong2 bh = *(const ulonglong2*)&Bs[kk*BN + c1];
            u64 rn[4] = {bl.x, bl.y, bh.x, bh.y};
#pragma unroll
            for (int i = 0; i < TM; i++)
#pragma unroll
                for (int j = 0; j < 4; j++)
                    acc[i][j] = fma2(rm[i], rn[j], acc[i][j]);
        }
        __syncthreads();
    }

#pragma unroll
    for (int i = 0; i < TM; i++) {
        int m = m0 + ty*TM + i;
#pragma unroll
        for (int g = 0; g < 2; g++) {
            int nb = g ? c1 : c0;
            float2 v0 = unpack2(acc[i][2*g]);
            float2 v1 = unpack2(acc[i][2*g+1]);
            float vv[4] = {v0.x, v0.y, v1.x, v1.y};
            float4 o;
            float* op = (float*)&o;
#pragma unroll
            for (int q = 0; q < 4; q++) {
                int n = nb + q;
                float c = vv[q];
                if (HASBIAS) c += bias[n];
                if (HASAUX)  c += aux[(size_t)m*BN + n];
                if (DOBN)    c = (c - bnm[n]) * rsqrtf(bnv[n] + BN_EPS_) * bng[n] + bnb[n];
                if (RELU)    c = fmaxf(c, 0.f);
                op[q] = c;
            }
            *(float4*)&C[(size_t)m*BN + nb] = o;
        }
    }
}

template<int BN, bool RELU, bool HASBIAS, bool HASAUX, bool DOBN>
__global__ void __launch_bounds__(128) k_gemm(
    const float* __restrict__ A, const float* __restrict__ Bw,
    float* __restrict__ C, int K,
    const float* __restrict__ bias, const float* __restrict__ aux,
    const float* __restrict__ bng, const float* __restrict__ bnb,
    const float* __restrict__ bnm, const float* __restrict__ bnv)
{
    __shared__ __align__(16) char smem[16*(64+2)*8 + 16*BN*4];
    gemm_body<BN,RELU,HASBIAS,HASAUX,DOBN>(A, Bw, C, K, blockIdx.x,
        bias, aux, bng, bnb, bnm, bnv, smem);
}

// Combined launch for the two independent K=768 GEMMs (fills the wave)
__global__ void __launch_bounds__(128) k_pair(
    const float* __restrict__ Z,
    const float* __restrict__ w1, const float* __restrict__ b1, float* __restrict__ H1,
    const float* __restrict__ proj, float* __restrict__ ZP)
{
    __shared__ __align__(16) char smem[16*(64+2)*8 + 16*128*4];
    if (blockIdx.y == 0)
        gemm_body<128,true,true,false,false>(Z, w1, H1, TH_, blockIdx.x,
            b1, nullptr, nullptr, nullptr, nullptr, nullptr, smem);
    else
        gemm_body<64,false,false,false,false>(Z, proj, ZP, TH_, blockIdx.x,
            nullptr, nullptr, nullptr, nullptr, nullptr, nullptr, smem);
}

// ---------------- K7: final stage, N=12, fused dual-GEMM + BN + transpose ----------------
__global__ void __launch_bounds__(128) k_final(
    const float* __restrict__ w3,  const float* __restrict__ b3,
    const float* __restrict__ pj,
    const float* __restrict__ bng, const float* __restrict__ bnb,
    const float* __restrict__ bnm, const float* __restrict__ bnv,
    float* __restrict__ out)
{
    __shared__ float w3s[HID2_*TOUT_];
    __shared__ float pjs[H_*TOUT_];
    const int tid = threadIdx.x;
    for (int idx = tid; idx < HID2_*TOUT_; idx += 128) w3s[idx] = w3[idx];
    for (int idx = tid; idx < H_*TOUT_;    idx += 128) pjs[idx] = pj[idx];
    __syncthreads();

    const int row = blockIdx.x * 128 + tid;
    float acc[TOUT_];
#pragma unroll
    for (int o = 0; o < TOUT_; o++) acc[o] = b3[o];

    const float4* hr = (const float4*)&g_h4[(size_t)row * HID2_];
#pragma unroll 4
    for (int k4 = 0; k4 < HID2_/4; k4++) {
        float4 hv = __ldg(&hr[k4]);
        float h[4] = {hv.x, hv.y, hv.z, hv.w};
#pragma unroll
        for (int q = 0; q < 4; q++) {
            int k = k4*4 + q;
#pragma unroll
            for (int o = 0; o < TOUT_; o++)
                acc[o] = fmaf(h[q], w3s[k*TOUT_ + o], acc[o]);
        }
    }
    const float4* er = (const float4*)&g_e[(size_t)row * H_];
#pragma unroll 4
    for (int k4 = 0; k4 < H_/4; k4++) {
        float4 ev = __ldg(&er[k4]);
        float e4[4] = {ev.x, ev.y, ev.z, ev.w};
#pragma unroll
        for (int q = 0; q < 4; q++) {
            int k = k4*4 + q;
#pragma unroll
            for (int o = 0; o < TOUT_; o++)
                acc[o] = fmaf(e4[q], pjs[k*TOUT_ + o], acc[o]);
        }
    }

    const int b = row / N_, n = row % N_;
#pragma unroll
    for (int o = 0; o < TOUT_; o++) {
        float c = (acc[o] - bnm[o]) * rsqrtf(bnv[o] + BN_EPS_) * bng[o] + bnb[o];
        out[((size_t)(b*TOUT_ + o))*N_ + n] = c;
    }
}

// ---------------- host launch ----------------
extern "C" void kernel_launch(void* const* d_in, const int* in_sizes, int n_in,
                              void* d_out, int out_size)
{
    const float* x        = (const float*)d_in[0];
    const float* W1       = (const float*)d_in[1];
    const float* W2       = (const float*)d_in[2];
    const float* enc_w1   = (const float*)d_in[3];
    const float* enc_b1   = (const float*)d_in[4];
    const float* enc_w2   = (const float*)d_in[5];
    const float* enc_b2   = (const float*)d_in[6];
    const float* enc_w3   = (const float*)d_in[7];
    const float* enc_b3   = (const float*)d_in[8];
    const float* enc_proj = (const float*)d_in[9];
    const float* enc_bn_g = (const float*)d_in[10];
    const float* enc_bn_b = (const float*)d_in[11];
    const float* enc_bn_m = (const float*)d_in[12];
    const float* enc_bn_v = (const float*)d_in[13];
    const float* dec_w1   = (const float*)d_in[14];
    const float* dec_b1   = (const float*)d_in[15];
    const float* dec_w2   = (const float*)d_in[16];
    const float* dec_b2   = (const float*)d_in[17];
    const float* dec_w3   = (const float*)d_in[18];
    const float* dec_b3   = (const float*)d_in[19];
    const float* dec_proj = (const float*)d_in[20];
    const float* dec_bn_g = (const float*)d_in[21];
    const float* dec_bn_b = (const float*)d_in[22];
    const float* dec_bn_m = (const float*)d_in[23];
    const float* dec_bn_v = (const float*)d_in[24];
    float* out = (float*)d_out;

    void *pz, *ph1, *pzp, *ph2, *pe, *ph3, *ph4;
    cudaGetSymbolAddress(&pz,  g_z);
    cudaGetSymbolAddress(&ph1, g_h1);
    cudaGetSymbolAddress(&pzp, g_zp);
    cudaGetSymbolAddress(&ph2, g_h2);
    cudaGetSymbolAddress(&pe,  g_e);
    cudaGetSymbolAddress(&ph3, g_h3);
    cudaGetSymbolAddress(&ph4, g_h4);
    float* Z  = (float*)pz;
    float* H1 = (float*)ph1;
    float* ZP = (float*)pzp;
    float* H2 = (float*)ph2;
    float* E  = (float*)pe;
    float* H3 = (float*)ph3;
    float* H4 = (float*)ph4;

    k_softmax<<<M_/128, 128>>>(x);
    k_graph  <<<dim3(N_/128, N_/JC, B_), 128>>>(x);
    k_gfin   <<<M_/128, 128>>>();
    k_buildz <<<(M_*TH_)/256, 256>>>(x, W1, W2);

    const int GB = M_ / 64;  // 192 blocks

    // h1 = relu(z @ enc_w1 + b1)  and  zp = z @ enc_proj  in one launch (K=768)
    k_pair<<<dim3(GB, 2), 128>>>(Z, enc_w1, enc_b1, H1, enc_proj, ZP);

    // h2 = relu(h1 @ enc_w2 + b2)  (K=128, N=128)
    k_gemm<128,true ,true ,false,false><<<GB,128>>>(H1, enc_w2, H2, HID2_,
        enc_b2, nullptr, nullptr, nullptr, nullptr, nullptr);
    // e = BN(h2 @ enc_w3 + b3 + zp) (K=128, N=64)
    k_gemm< 64,false,true ,true ,true ><<<GB,128>>>(H2, enc_w3, E, HID2_,
        enc_b3, ZP, enc_bn_g, enc_bn_b, enc_bn_m, enc_bn_v);
    // h3 = relu(e @ dec_w1 + db1)  (K=64, N=128)
    k_gemm<128,true ,true ,false,false><<<GB,128>>>(E, dec_w1, H3, H_,
        dec_b1, nullptr, nullptr, nullptr, nullptr, nullptr);
    // h4 = relu(h3 @ dec_w2 + db2) (K=128, N=128)
    k_gemm<128,true ,true ,false,false><<<GB,128>>>(H3, dec_w2, H4, HID2_,
        dec_b2, nullptr, nullptr, nullptr, nullptr, nullptr);

    // out = transpose(BN(h4 @ dec_w3 + db3 + e @ dec_proj))
    k_final<<<M_/128, 128>>>(dec_w3, dec_b3, dec_proj,
                             dec_bn_g, dec_bn_b, dec_bn_m, dec_bn_v, out);
}

// round 3
// speedup vs baseline: 1.7779x; 1.0970x over previous
#include <cuda_runtime.h>
#include <math.h>

#define B_    8
#define T_    12
#define N_    1536
#define H_    64
#define TH_   768
#define HID2_ 128
#define TOUT_ 12
#define M_    (B_*N_)          // 12288
#define DELTA_   0.5f
#define ALPHA_   0.3f
#define KHOPS_   3.0f
#define KL_EPS_  1e-10f
#define BN_EPS_  1e-5f
#define DEG_MIN_ 1e-6f

typedef unsigned long long u64;

// ---------------- packed fp32x2 helpers (sm_103a FFMA2) ----------------
__device__ __forceinline__ u64 fma2(u64 a, u64 b, u64 c) {
    u64 d;
    asm("fma.rn.f32x2 %0, %1, %2, %3;" : "=l"(d) : "l"(a), "l"(b), "l"(c));
    return d;
}
__device__ __forceinline__ u64 pack2(float x, float y) {
    u64 d;
    asm("mov.b64 %0, {%1, %2};" : "=l"(d) : "f"(x), "f"(y));
    return d;
}
__device__ __forceinline__ float2 unpack2(u64 v) {
    float2 r;
    asm("mov.b64 {%0, %1}, %2;" : "=f"(r.x), "=f"(r.y) : "l"(v));
    return r;
}

// ---------------- device scratch ----------------
__device__ __align__(16) float g_p [M_*T_];
__device__ __align__(16) float g_lp[M_*T_];
__device__ float g_s  [M_];
__device__ float g_deg[M_];
__device__ float g_ind[M_];
__device__ __align__(16) float g_af[M_*T_];
__device__ __align__(16) float g_ab[M_*T_];
__device__ __align__(16) float g_gg[M_*T_];
__device__ __align__(16) float g_z [(size_t)M_*TH_];
__device__ __align__(16) float g_h1[(size_t)M_*HID2_];
__device__ __align__(16) float g_zp[(size_t)M_*H_];
__device__ __align__(16) float g_h2[(size_t)M_*HID2_];
__device__ __align__(16) float g_e [(size_t)M_*H_];
__device__ __align__(16) float g_h3[(size_t)M_*HID2_];
__device__ __align__(16) float g_h4[(size_t)M_*HID2_];

// ---------------- K1: per-node softmax over T, logp, s; also zeros accumulators ----------------
__global__ void __launch_bounds__(64) k_softmax(const float* __restrict__ x) {
    int bn = blockIdx.x * 64 + threadIdx.x;
    if (bn >= M_) return;
    int b = bn / N_, n = bn % N_;
    float v[T_];
    float mx = -1e30f;
#pragma unroll
    for (int t = 0; t < T_; t++) {
        v[t] = x[((size_t)(b*T_ + t))*N_ + n];
        mx = fmaxf(mx, v[t]);
    }
    float sum = 0.f;
#pragma unroll
    for (int t = 0; t < T_; t++) { v[t] = expf(v[t] - mx); sum += v[t]; }
    float inv = 1.f / sum;
    float s = 0.f;
    size_t base = (size_t)bn * T_;
#pragma unroll
    for (int t = 0; t < T_; t++) {
        float p  = v[t] * inv;
        float lp = logf(p + KL_EPS_);
        g_p [base + t] = p;
        g_lp[base + t] = lp;
        g_af[base + t] = 0.f;
        g_ab[base + t] = 0.f;
        s = fmaf(p, lp, s);
    }
    g_s[bn] = s;
    g_deg[bn] = 0.f;
    g_ind[bn] = 0.f;
}

// ---------------- K2: graph threshold + masked aggregation (f32x2 packed over t) ----------------
#define JC 256
__global__ void __launch_bounds__(128) k_graph(const float* __restrict__ x) {
    __shared__ __align__(16) float psh[JC*T_];
    __shared__ __align__(16) float lsh[JC*T_];
    __shared__ __align__(16) float xsh[JC*T_];
    __shared__ float ssh[JC];

    const int tid = threadIdx.x;
    const int b   = blockIdx.z;
    const int i   = blockIdx.x * 128 + tid;
    const int j0  = blockIdx.y * JC;
    const int bN  = b * N_;

    {
        size_t base = (size_t)(bN + j0) * T_;
        const float4* sp = (const float4*)(g_p  + base);
        const float4* sl = (const float4*)(g_lp + base);
#pragma unroll
        for (int q = 0; q < (JC*T_/4)/128; q++) {
            int idx = q*128 + tid;
            ((float4*)psh)[idx] = sp[idx];
            ((float4*)lsh)[idx] = sl[idx];
        }
#pragma unroll
        for (int t = 0; t < T_; t++) {
            xsh[tid*T_ + t]        = x[((size_t)(b*T_ + t))*N_ + j0 + tid];
            xsh[(tid+128)*T_ + t]  = x[((size_t)(b*T_ + t))*N_ + j0 + tid + 128];
        }
        ssh[tid]       = g_s[bN + j0 + tid];
        ssh[tid + 128] = g_s[bN + j0 + tid + 128];
    }

    u64 pi2[6], li2[6];
    {
        const ulonglong2* pp = (const ulonglong2*)(g_p  + (size_t)(bN + i)*T_);
        const ulonglong2* lp = (const ulonglong2*)(g_lp + (size_t)(bN + i)*T_);
#pragma unroll
        for (int q = 0; q < 3; q++) {
            ulonglong2 a = pp[q]; pi2[2*q] = a.x; pi2[2*q+1] = a.y;
            ulonglong2 c = lp[q]; li2[2*q] = c.x; li2[2*q+1] = c.y;
        }
    }
    const float si = g_s[bN + i];

    u64 accf2[6], accb2[6];
#pragma unroll
    for (int t = 0; t < 6; t++) { accf2[t] = 0ull; accb2[t] = 0ull; }
    float deg = 0.f, ind = 0.f;

    __syncthreads();

    for (int jj = 0; jj < JC; jj++) {
        const u64* pj2 = (const u64*)(psh + jj*T_);
        const u64* lj2 = (const u64*)(lsh + jj*T_);
        u64 d1 = 0ull, d2 = 0ull;
#pragma unroll
        for (int t = 0; t < 6; t++) {
            d1 = fma2(pi2[t], lj2[t], d1);   // p_i . logp_j
            d2 = fma2(pj2[t], li2[t], d2);   // p_j . logp_i
        }
        float2 r1 = unpack2(d1);
        float2 r2 = unpack2(d2);
        float d1s = r1.x + r1.y;
        float d2s = r2.x + r2.y;
        float mf = ((si - d1s)      < DELTA_) ? 1.f : 0.f;  // A[i,j]
        float mb = ((ssh[jj] - d2s) < DELTA_) ? 1.f : 0.f;  // A[j,i]
        deg += mf; ind += mb;
        u64 mf2 = pack2(mf, mf);
        u64 mb2 = pack2(mb, mb);
        const u64* xj2 = (const u64*)(xsh + jj*T_);
#pragma unroll
        for (int t = 0; t < 6; t++) {
            u64 xv = xj2[t];
            accf2[t] = fma2(mf2, xv, accf2[t]);
            accb2[t] = fma2(mb2, xv, accb2[t]);
        }
    }

    atomicAdd(&g_deg[bN + i], deg);
    atomicAdd(&g_ind[bN + i], ind);
    size_t obase = (size_t)(bN + i) * T_;
#pragma unroll
    for (int t = 0; t < 6; t++) {
        float2 f = unpack2(accf2[t]);
        float2 g = unpack2(accb2[t]);
        atomicAdd(&g_af[obase + 2*t    ], f.x);
        atomicAdd(&g_af[obase + 2*t + 1], f.y);
        atomicAdd(&g_ab[obase + 2*t    ], g.x);
        atomicAdd(&g_ab[obase + 2*t + 1], g.y);
    }
}

// ---------------- K2b: finalize message (per-row reciprocal) ----------------
__global__ void k_gfin() {
    int row = blockIdx.x * 128 + threadIdx.x;
    if (row >= M_) return;
    float rf = (KHOPS_ * ALPHA_)        * __frcp_rn(fmaxf(g_deg[row], DEG_MIN_));
    float rb = (KHOPS_ * (1.f-ALPHA_))  * __frcp_rn(fmaxf(g_ind[row], DEG_MIN_));
    size_t base = (size_t)row * T_;
#pragma unroll
    for (int t = 0; t < T_; t++)
        g_gg[base + t] = rf * g_af[base + t] + rb * g_ab[base + t];
}

// ---------------- K3: build z = relu(x*W1 + g*W2), float4 over h ----------------
__global__ void __launch_bounds__(256) k_buildz(const float* __restrict__ x,
                                                const float* __restrict__ W1,
                                                const float* __restrict__ W2) {
    int idx4 = blockIdx.x * 256 + threadIdx.x;      // < M_*TH_/4
    if (idx4 >= M_*TH_/4) return;
    int row = idx4 / (TH_/4);                        // /192
    int c4  = idx4 % (TH_/4);
    int t   = c4 >> 4;                               // /16
    int h4  = (c4 & 15) * 4;
    int b = row / N_, n = row % N_;
    float xv = x[((size_t)(b*T_ + t))*N_ + n];
    float gg = g_gg[row*T_ + t];
    float4 w1 = *(const float4*)&W1[h4];
    float4 w2 = *(const float4*)&W2[h4];
    float4 o;
    o.x = fmaxf(fmaf(xv, w1.x, gg * w2.x), 0.f);
    o.y = fmaxf(fmaf(xv, w1.y, gg * w2.y), 0.f);
    o.z = fmaxf(fmaf(xv, w1.z, gg * w2.z), 0.f);
    o.w = fmaxf(fmaf(xv, w1.w, gg * w2.w), 0.f);
    *(float4*)&g_z[(size_t)idx4 * 4] = o;
}

// ---------------- f32x2 GEMM body: C(M,BN) = A(M,K) @ Bw(K,BN) + epilogue ----------------
// 128 threads. Unified per-thread tile TM=4 x TN=8 (two 4-col groups).
// BN=128: BM=32, TXC=16. BN=64: BM=64, TXC=8.
// A duplicated (v,v) in smem -> broadcast LDS.128 yields packed pairs.
template<int BM, int BN, bool RELU, bool HASBIAS, bool HASAUX, bool DOBN>
__device__ __forceinline__ void gemm_body(
    const float* __restrict__ A, const float* __restrict__ Bw,
    float* __restrict__ C, int K, int mblk,
    const float* __restrict__ bias, const float* __restrict__ aux,
    const float* __restrict__ bng, const float* __restrict__ bnb,
    const float* __restrict__ bnm, const float* __restrict__ bnv,
    char* smem)
{
    constexpr int BK = 16;
    constexpr int TXC = BN / 8;
    constexpr int TM  = 4;
    constexpr int PITCH = BM + 2;   // float2 units
    float2* Asd = (float2*)smem;                                  // BK*PITCH float2
    float*  Bs  = (float*)(smem + BK*PITCH*sizeof(float2));       // BK*BN floats

    const int tid  = threadIdx.x;
    const int lane = tid & 31, warp = tid >> 5;
    const int tx = lane % TXC;
    const int ty = warp * (32/TXC) + lane / TXC;
    const int m0 = mblk * BM;
    const int c0 = tx * 4;
    const int c1 = BN/2 + tx * 4;

    u64 acc[TM][4];
#pragma unroll
    for (int i = 0; i < TM; i++)
#pragma unroll
        for (int j = 0; j < 4; j++) acc[i][j] = 0ull;

    for (int k0 = 0; k0 < K; k0 += BK) {
        // fill Asd (duplicated): BM*BK values, k-fast coalesced
#pragma unroll
        for (int q = 0; q < BM*BK/128; q++) {
            int idx = q*128 + tid;
            int k = idx & (BK-1);
            int m = idx >> 4;
            float v = A[(size_t)(m0 + m)*K + k0 + k];
            Asd[k*PITCH + m] = make_float2(v, v);
        }
        // fill Bs: BK*BN floats, float4 per thread
#pragma unroll
        for (int q = 0; q < BK*BN/512; q++) {
            int idx4 = q*128 + tid;
            int k  = idx4 / (BN/4);
            int n4 = (idx4 % (BN/4)) * 4;
            *(float4*)&Bs[k*BN + n4] = *(const float4*)&Bw[(size_t)(k0 + k)*BN + n4];
        }
        __syncthreads();
#pragma unroll
        for (int kk = 0; kk < BK; kk++) {
            ulonglong2 a01 = *(const ulonglong2*)&Asd[kk*PITCH + ty*TM];
            ulonglong2 a23 = *(const ulonglong2*)&Asd[kk*PITCH + ty*TM + 2];
            u64 rm[TM] = {a01.x, a01.y, a23.x, a23.y};
            ulonglong2 bl = *(const ulonglong2*)&Bs[kk*BN + c0];
            ulonglong2 bh = *(const ulonglong2*)&Bs[kk*BN + c1];
            u64 rn[4] = {bl.x, bl.y, bh.x, bh.y};
#pragma unroll
            for (int i = 0; i < TM; i++)
#pragma unroll
                for (int j = 0; j < 4; j++)
                    acc[i][j] = fma2(rm[i], rn[j], acc[i][j]);
        }
        __syncthreads();
    }

#pragma unroll
    for (int i = 0; i < TM; i++) {
        int m = m0 + ty*TM + i;
#pragma unroll
        for (int g = 0; g < 2; g++) {
            int nb = g ? c1 : c0;
            float2 v0 = unpack2(acc[i][2*g]);
            float2 v1 = unpack2(acc[i][2*g+1]);
            float vv[4] = {v0.x, v0.y, v1.x, v1.y};
            float4 o;
            float* op = (float*)&o;
#pragma unroll
            for (int q = 0; q < 4; q++) {
                int n = nb + q;
                float c = vv[q];
                if (HASBIAS) c += bias[n];
                if (HASAUX)  c += aux[(size_t)m*BN + n];
                if (DOBN)    c = (c - bnm[n]) * rsqrtf(bnv[n] + BN_EPS_) * bng[n] + bnb[n];
                if (RELU)    c = fmaxf(c, 0.f);
                op[q] = c;
            }
            *(float4*)&C[(size_t)m*BN + nb] = o;
        }
    }
}

#define SMEM_BYTES (16*(64+2)*8 + 16*128*4)   // max of both configs (=12544 for 32/128 & 64/64 -> use union upper bound)

template<int BM, int BN, bool RELU, bool HASBIAS, bool HASAUX, bool DOBN>
__global__ void __launch_bounds__(128) k_gemm(
    const float* __restrict__ A, const float* __restrict__ Bw,
    float* __restrict__ C, int K,
    const float* __restrict__ bias, const float* __restrict__ aux,
    const float* __restrict__ bng, const float* __restrict__ bnb,
    const float* __restrict__ bnm, const float* __restrict__ bnv)
{
    __shared__ __align__(16) char smem[SMEM_BYTES];
    gemm_body<BM,BN,RELU,HASBIAS,HASAUX,DOBN>(A, Bw, C, K, blockIdx.x,
        bias, aux, bng, bnb, bnm, bnv, smem);
}

// Combined launch: h1 (384 tiles of BM=32, BN=128) + zp (192 tiles of BM=64, BN=64)
__global__ void __launch_bounds__(128) k_pair(
    const float* __restrict__ Z,
    const float* __restrict__ w1, const float* __restrict__ b1, float* __restrict__ H1,
    const float* __restrict__ proj, float* __restrict__ ZP)
{
    __shared__ __align__(16) char smem[SMEM_BYTES];
    int bx = blockIdx.x;
    if (bx < M_/32)
        gemm_body<32,128,true,true,false,false>(Z, w1, H1, TH_, bx,
            b1, nullptr, nullptr, nullptr, nullptr, nullptr, smem);
    else
        gemm_body<64,64,false,false,false,false>(Z, proj, ZP, TH_, bx - M_/32,
            nullptr, nullptr, nullptr, nullptr, nullptr, nullptr, smem);
}

// ---------------- K7: final stage, N=12, fused dual-GEMM + BN + transpose ----------------
__global__ void __launch_bounds__(64) k_final(
    const float* __restrict__ w3,  const float* __restrict__ b3,
    const float* __restrict__ pj,
    const float* __restrict__ bng, const float* __restrict__ bnb,
    const float* __restrict__ bnm, const float* __restrict__ bnv,
    float* __restrict__ out)
{
    __shared__ float w3s[HID2_*TOUT_];
    __shared__ float pjs[H_*TOUT_];
    const int tid = threadIdx.x;
    for (int idx = tid; idx < HID2_*TOUT_; idx += 64) w3s[idx] = w3[idx];
    for (int idx = tid; idx < H_*TOUT_;    idx += 64) pjs[idx] = pj[idx];
    __syncthreads();

    const int row = blockIdx.x * 64 + tid;
    float acc[TOUT_];
#pragma unroll
    for (int o = 0; o < TOUT_; o++) acc[o] = b3[o];

    const float4* hr = (const float4*)&g_h4[(size_t)row * HID2_];
#pragma unroll 4
    for (int k4 = 0; k4 < HID2_/4; k4++) {
        float4 hv = __ldg(&hr[k4]);
        float h[4] = {hv.x, hv.y, hv.z, hv.w};
#pragma unroll
        for (int q = 0; q < 4; q++) {
            int k = k4*4 + q;
#pragma unroll
            for (int o = 0; o < TOUT_; o++)
                acc[o] = fmaf(h[q], w3s[k*TOUT_ + o], acc[o]);
        }
    }
    const float4* er = (const float4*)&g_e[(size_t)row * H_];
#pragma unroll 4
    for (int k4 = 0; k4 < H_/4; k4++) {
        float4 ev = __ldg(&er[k4]);
        float e4[4] = {ev.x, ev.y, ev.z, ev.w};
#pragma unroll
        for (int q = 0; q < 4; q++) {
            int k = k4*4 + q;
#pragma unroll
            for (int o = 0; o < TOUT_; o++)
                acc[o] = fmaf(e4[q], pjs[k*TOUT_ + o], acc[o]);
        }
    }

    const int b = row / N_, n = row % N_;
#pragma unroll
    for (int o = 0; o < TOUT_; o++) {
        float c = (acc[o] - bnm[o]) * rsqrtf(bnv[o] + BN_EPS_) * bng[o] + bnb[o];
        out[((size_t)(b*TOUT_ + o))*N_ + n] = c;
    }
}

// ---------------- host launch ----------------
extern "C" void kernel_launch(void* const* d_in, const int* in_sizes, int n_in,
                              void* d_out, int out_size)
{
    const float* x        = (const float*)d_in[0];
    const float* W1       = (const float*)d_in[1];
    const float* W2       = (const float*)d_in[2];
    const float* enc_w1   = (const float*)d_in[3];
    const float* enc_b1   = (const float*)d_in[4];
    const float* enc_w2   = (const float*)d_in[5];
    const float* enc_b2   = (const float*)d_in[6];
    const float* enc_w3   = (const float*)d_in[7];
    const float* enc_b3   = (const float*)d_in[8];
    const float* enc_proj = (const float*)d_in[9];
    const float* enc_bn_g = (const float*)d_in[10];
    const float* enc_bn_b = (const float*)d_in[11];
    const float* enc_bn_m = (const float*)d_in[12];
    const float* enc_bn_v = (const float*)d_in[13];
    const float* dec_w1   = (const float*)d_in[14];
    const float* dec_b1   = (const float*)d_in[15];
    const float* dec_w2   = (const float*)d_in[16];
    const float* dec_b2   = (const float*)d_in[17];
    const float* dec_w3   = (const float*)d_in[18];
    const float* dec_b3   = (const float*)d_in[19];
    const float* dec_proj = (const float*)d_in[20];
    const float* dec_bn_g = (const float*)d_in[21];
    const float* dec_bn_b = (const float*)d_in[22];
    const float* dec_bn_m = (const float*)d_in[23];
    const float* dec_bn_v = (const float*)d_in[24];
    float* out = (float*)d_out;

    void *pz, *ph1, *pzp, *ph2, *pe, *ph3, *ph4;
    cudaGetSymbolAddress(&pz,  g_z);
    cudaGetSymbolAddress(&ph1, g_h1);
    cudaGetSymbolAddress(&pzp, g_zp);
    cudaGetSymbolAddress(&ph2, g_h2);
    cudaGetSymbolAddress(&pe,  g_e);
    cudaGetSymbolAddress(&ph3, g_h3);
    cudaGetSymbolAddress(&ph4, g_h4);
    float* Z  = (float*)pz;
    float* H1 = (float*)ph1;
    float* ZP = (float*)pzp;
    float* H2 = (float*)ph2;
    float* E  = (float*)pe;
    float* H3 = (float*)ph3;
    float* H4 = (float*)ph4;

    k_softmax<<<M_/64, 64>>>(x);
    k_graph  <<<dim3(N_/128, N_/JC, B_), 128>>>(x);
    k_gfin   <<<M_/128, 128>>>();
    k_buildz <<<(M_*TH_/4)/256, 256>>>(x, W1, W2);

    const int GB128 = M_/32;   // 384 tiles for BN=128 kernels
    const int GB64  = M_/64;   // 192 tiles for BN=64 kernels

    // h1 = relu(z @ enc_w1 + b1)  and  zp = z @ enc_proj  in one 576-block launch
    k_pair<<<GB128 + GB64, 128>>>(Z, enc_w1, enc_b1, H1, enc_proj, ZP);

    // h2 = relu(h1 @ enc_w2 + b2)  (K=128, N=128)
    k_gemm<32,128,true ,true ,false,false><<<GB128,128>>>(H1, enc_w2, H2, HID2_,
        enc_b2, nullptr, nullptr, nullptr, nullptr, nullptr);
    // e = BN(h2 @ enc_w3 + b3 + zp) (K=128, N=64)
    k_gemm<64, 64,false,true ,true ,true ><<<GB64,128>>>(H2, enc_w3, E, HID2_,
        enc_b3, ZP, enc_bn_g, enc_bn_b, enc_bn_m, enc_bn_v);
    // h3 = relu(e @ dec_w1 + db1)  (K=64, N=128)
    k_gemm<32,128,true ,true ,false,false><<<GB128,128>>>(E, dec_w1, H3, H_,
        dec_b1, nullptr, nullptr, nullptr, nullptr, nullptr);
    // h4 = relu(h3 @ dec_w2 + db2) (K=128, N=128)
    k_gemm<32,128,true ,true ,false,false><<<GB128,128>>>(H3, dec_w2, H4, HID2_,
        dec_b2, nullptr, nullptr, nullptr, nullptr, nullptr);

    // out = transpose(BN(h4 @ dec_w3 + db3 + e @ dec_proj))
    k_final<<<M_/64, 64>>>(dec_w3, dec_b3, dec_proj,
                           dec_bn_g, dec_bn_b, dec_bn_m, dec_bn_v, out);
}

// round 5
// speedup vs baseline: 2.2919x; 1.2891x over previous
#include <cuda_runtime.h>
#include <cuda_bf16.h>
#include <math.h>
#include <stdint.h>

#define B_    8
#define T_    12
#define N_    1536
#define H_    64
#define TH_   768
#define HID2_ 128
#define TOUT_ 12
#define M_    (B_*N_)          // 12288
#define DELTA_   0.5f
#define ALPHA_   0.3f
#define KHOPS_   3.0f
#define KL_EPS_  1e-10f
#define BN_EPS_  1e-5f
#define DEG_MIN_ 1e-6f

typedef unsigned long long u64;

// ---------------- packed fp32x2 helpers (sm_103a FFMA2) ----------------
__device__ __forceinline__ u64 fma2(u64 a, u64 b, u64 c) {
    u64 d;
    asm("fma.rn.f32x2 %0, %1, %2, %3;" : "=l"(d) : "l"(a), "l"(b), "l"(c));
    return d;
}
__device__ __forceinline__ u64 pack2(float x, float y) {
    u64 d;
    asm("mov.b64 %0, {%1, %2};" : "=l"(d) : "f"(x), "f"(y));
    return d;
}
__device__ __forceinline__ float2 unpack2(u64 v) {
    float2 r;
    asm("mov.b64 {%0, %1}, %2;" : "=f"(r.x), "=f"(r.y) : "l"(v));
    return r;
}

// ---------------- warp mma.sync bf16 (standard PTX, no sm_103a gating) ----------------
__device__ __forceinline__ void mma_bf16(float* c,
    uint32_t a0, uint32_t a1, uint32_t a2, uint32_t a3,
    uint32_t b0, uint32_t b1)
{
    asm volatile(
        "mma.sync.aligned.m16n8k16.row.col.f32.bf16.bf16.f32 "
        "{%0,%1,%2,%3}, {%4,%5,%6,%7}, {%8,%9}, {%0,%1,%2,%3};"
        : "+f"(c[0]), "+f"(c[1]), "+f"(c[2]), "+f"(c[3])
        : "r"(a0), "r"(a1), "r"(a2), "r"(a3), "r"(b0), "r"(b1));
}

// ---------------- device scratch ----------------
__device__ __align__(16) float g_p [M_*T_];
__device__ __align__(16) float g_lp[M_*T_];
__device__ float g_s  [M_];
__device__ float g_deg[M_];
__device__ float g_ind[M_];
__device__ __align__(16) float g_af[M_*T_];
__device__ __align__(16) float g_ab[M_*T_];
__device__ __align__(16) float g_gg[M_*T_];
__device__ __align__(16) __nv_bfloat16 g_zh[(size_t)M_*TH_];
__device__ __align__(16) __nv_bfloat16 g_zl[(size_t)M_*TH_];
__device__ __align__(16) __nv_bfloat16 g_wh[(size_t)(HID2_+H_)*TH_];  // [192 n][768 k]
__device__ __align__(16) __nv_bfloat16 g_wl[(size_t)(HID2_+H_)*TH_];
__device__ __align__(16) float g_h1[(size_t)M_*HID2_];
__device__ __align__(16) float g_zp[(size_t)M_*H_];
__device__ __align__(16) float g_h2[(size_t)M_*HID2_];
__device__ __align__(16) float g_e [(size_t)M_*H_];
__device__ __align__(16) float g_h3[(size_t)M_*HID2_];
__device__ __align__(16) float g_h4[(size_t)M_*HID2_];

// ---------------- K1: per-node softmax over T, logp, s; zeros accumulators ----------------
__global__ void __launch_bounds__(64) k_softmax(const float* __restrict__ x) {
    int bn = blockIdx.x * 64 + threadIdx.x;
    if (bn >= M_) return;
    int b = bn / N_, n = bn % N_;
    float v[T_];
    float mx = -1e30f;
#pragma unroll
    for (int t = 0; t < T_; t++) {
        v[t] = x[((size_t)(b*T_ + t))*N_ + n];
        mx = fmaxf(mx, v[t]);
    }
    float sum = 0.f;
#pragma unroll
    for (int t = 0; t < T_; t++) { v[t] = expf(v[t] - mx); sum += v[t]; }
    float inv = 1.f / sum;
    float s = 0.f;
    size_t base = (size_t)bn * T_;
#pragma unroll
    for (int t = 0; t < T_; t++) {
        float p  = v[t] * inv;
        float lp = logf(p + KL_EPS_);
        g_p [base + t] = p;
        g_lp[base + t] = lp;
        g_af[base + t] = 0.f;
        g_ab[base + t] = 0.f;
        s = fmaf(p, lp, s);
    }
    g_s[bn] = s;
    g_deg[bn] = 0.f;
    g_ind[bn] = 0.f;
}

// ---------------- K2: graph threshold + masked aggregation ----------------
#define JC 256
__global__ void __launch_bounds__(128) k_graph(const float* __restrict__ x) {
    __shared__ __align__(16) float psh[JC*T_];
    __shared__ __align__(16) float lsh[JC*T_];
    __shared__ __align__(16) float xsh[JC*T_];
    __shared__ float ssh[JC];

    const int tid = threadIdx.x;
    const int b   = blockIdx.z;
    const int i   = blockIdx.x * 128 + tid;
    const int j0  = blockIdx.y * JC;
    const int bN  = b * N_;

    {
        size_t base = (size_t)(bN + j0) * T_;
        const float4* sp = (const float4*)(g_p  + base);
        const float4* sl = (const float4*)(g_lp + base);
#pragma unroll
        for (int q = 0; q < (JC*T_/4)/128; q++) {
            int idx = q*128 + tid;
            ((float4*)psh)[idx] = sp[idx];
            ((float4*)lsh)[idx] = sl[idx];
        }
#pragma unroll
        for (int t = 0; t < T_; t++) {
            xsh[tid*T_ + t]        = x[((size_t)(b*T_ + t))*N_ + j0 + tid];
            xsh[(tid+128)*T_ + t]  = x[((size_t)(b*T_ + t))*N_ + j0 + tid + 128];
        }
        ssh[tid]       = g_s[bN + j0 + tid];
        ssh[tid + 128] = g_s[bN + j0 + tid + 128];
    }

    u64 pi2[6], li2[6];
    {
        const ulonglong2* pp = (const ulonglong2*)(g_p  + (size_t)(bN + i)*T_);
        const ulonglong2* lp = (const ulonglong2*)(g_lp + (size_t)(bN + i)*T_);
#pragma unroll
        for (int q = 0; q < 3; q++) {
            ulonglong2 a = pp[q]; pi2[2*q] = a.x; pi2[2*q+1] = a.y;
            ulonglong2 c = lp[q]; li2[2*q] = c.x; li2[2*q+1] = c.y;
        }
    }
    const float si = g_s[bN + i];

    u64 accf2[6], accb2[6];
#pragma unroll
    for (int t = 0; t < 6; t++) { accf2[t] = 0ull; accb2[t] = 0ull; }
    float deg = 0.f, ind = 0.f;

    __syncthreads();

    for (int jj = 0; jj < JC; jj++) {
        const u64* pj2 = (const u64*)(psh + jj*T_);
        const u64* lj2 = (const u64*)(lsh + jj*T_);
        u64 d1 = 0ull, d2 = 0ull;
#pragma unroll
        for (int t = 0; t < 6; t++) {
            d1 = fma2(pi2[t], lj2[t], d1);
            d2 = fma2(pj2[t], li2[t], d2);
        }
        float2 r1 = unpack2(d1);
        float2 r2 = unpack2(d2);
        float d1s = r1.x + r1.y;
        float d2s = r2.x + r2.y;
        float mf = ((si - d1s)      < DELTA_) ? 1.f : 0.f;
        float mb = ((ssh[jj] - d2s) < DELTA_) ? 1.f : 0.f;
        deg += mf; ind += mb;
        u64 mf2 = pack2(mf, mf);
        u64 mb2 = pack2(mb, mb);
        const u64* xj2 = (const u64*)(xsh + jj*T_);
#pragma unroll
        for (int t = 0; t < 6; t++) {
            u64 xv = xj2[t];
            accf2[t] = fma2(mf2, xv, accf2[t]);
            accb2[t] = fma2(mb2, xv, accb2[t]);
        }
    }

    atomicAdd(&g_deg[bN + i], deg);
    atomicAdd(&g_ind[bN + i], ind);
    size_t obase = (size_t)(bN + i) * T_;
#pragma unroll
    for (int t = 0; t < 6; t++) {
        float2 f = unpack2(accf2[t]);
        float2 g = unpack2(accb2[t]);
        atomicAdd(&g_af[obase + 2*t    ], f.x);
        atomicAdd(&g_af[obase + 2*t + 1], f.y);
        atomicAdd(&g_ab[obase + 2*t    ], g.x);
        atomicAdd(&g_ab[obase + 2*t + 1], g.y);
    }
}

// ---------------- K2b: finalize message ----------------
__global__ void k_gfin() {
    int row = blockIdx.x * 128 + threadIdx.x;
    if (row >= M_) return;
    float rf = (KHOPS_ * ALPHA_)        * __frcp_rn(fmaxf(g_deg[row], DEG_MIN_));
    float rb = (KHOPS_ * (1.f-ALPHA_))  * __frcp_rn(fmaxf(g_ind[row], DEG_MIN_));
    size_t base = (size_t)row * T_;
#pragma unroll
    for (int t = 0; t < T_; t++)
        g_gg[base + t] = rf * g_af[base + t] + rb * g_ab[base + t];
}

// ---------------- K3: build z = relu(x*W1 + g*W2), split to bf16 hi/lo ----------------
__global__ void __launch_bounds__(256) k_buildz(const float* __restrict__ x,
                                                const float* __restrict__ W1,
                                                const float* __restrict__ W2) {
    int idx4 = blockIdx.x * 256 + threadIdx.x;
    if (idx4 >= M_*TH_/4) return;
    int row = idx4 / (TH_/4);
    int c4  = idx4 % (TH_/4);
    int t   = c4 >> 4;
    int h4  = (c4 & 15) * 4;
    int b = row / N_, n = row % N_;
    float xv = x[((size_t)(b*T_ + t))*N_ + n];
    float gg = g_gg[row*T_ + t];
    float4 w1 = *(const float4*)&W1[h4];
    float4 w2 = *(const float4*)&W2[h4];
    float v0 = fmaxf(fmaf(xv, w1.x, gg * w2.x), 0.f);
    float v1 = fmaxf(fmaf(xv, w1.y, gg * w2.y), 0.f);
    float v2 = fmaxf(fmaf(xv, w1.z, gg * w2.z), 0.f);
    float v3 = fmaxf(fmaf(xv, w1.w, gg * w2.w), 0.f);
    __nv_bfloat16 h0 = __float2bfloat16(v0), h1 = __float2bfloat16(v1);
    __nv_bfloat16 h2 = __float2bfloat16(v2), h3 = __float2bfloat16(v3);
    __nv_bfloat16 l0 = __float2bfloat16(v0 - __bfloat162float(h0));
    __nv_bfloat16 l1 = __float2bfloat16(v1 - __bfloat162float(h1));
    __nv_bfloat16 l2 = __float2bfloat16(v2 - __bfloat162float(h2));
    __nv_bfloat16 l3 = __float2bfloat16(v3 - __bfloat162float(h3));
    size_t o = (size_t)idx4 * 4;
    *(__nv_bfloat162*)&g_zh[o]   = __nv_bfloat162{h0, h1};
    *(__nv_bfloat162*)&g_zh[o+2] = __nv_bfloat162{h2, h3};
    *(__nv_bfloat162*)&g_zl[o]   = __nv_bfloat162{l0, l1};
    *(__nv_bfloat162*)&g_zl[o+2] = __nv_bfloat162{l2, l3};
}

// ---------------- K3b: transpose+split weights to [192 n][768 k] bf16 hi/lo ----------------
__global__ void __launch_bounds__(256) k_transpose(const float* __restrict__ w1,
                                                   const float* __restrict__ proj) {
    int idx = blockIdx.x * 256 + threadIdx.x;
    if (idx >= (HID2_+H_)*TH_) return;
    int n = idx / TH_, k = idx % TH_;
    float v = (n < HID2_) ? w1[(size_t)k*HID2_ + n] : proj[(size_t)k*H_ + (n - HID2_)];
    __nv_bfloat16 h = __float2bfloat16(v);
    g_wh[idx] = h;
    g_wl[idx] = __float2bfloat16(v - __bfloat162float(h));
}

// ---------------- K4: mma.sync bf16x3 fused GEMM: h1 = relu(Z@w1+b1), zp = Z@proj ----------------
// Grid (96 m-tiles, 3 n-slices of 64). 256 thr = 8 warps over M=128 (16 rows each).
// bf16x3: acc += zh*wh + zh*wl + zl*wh (single fp32 accumulator).
#define KPCH 40   // smem pitch in bf16 units (conflict-free fragment LDS)
__global__ void __launch_bounds__(256) k_pair_mma(const float* __restrict__ b1v) {
    __shared__ __align__(16) __nv_bfloat16 Ah[128*KPCH];
    __shared__ __align__(16) __nv_bfloat16 Al[128*KPCH];
    __shared__ __align__(16) __nv_bfloat16 Bh[64*KPCH];
    __shared__ __align__(16) __nv_bfloat16 Bl[64*KPCH];

    const int tid  = threadIdx.x;
    const int w    = tid >> 5, lane = tid & 31;
    const int m0   = blockIdx.x * 128;
    const int n0   = blockIdx.y * 64;   // concat col base (0,64 -> h1; 128 -> zp)

    float acc[8][4];
#pragma unroll
    for (int t = 0; t < 8; t++)
#pragma unroll
        for (int j = 0; j < 4; j++) acc[t][j] = 0.f;

    const int arow = w*16 + (lane >> 2);
    const int koff = (lane & 3) * 2;

    for (int k0 = 0; k0 < TH_; k0 += 32) {
        // fill A: 128 rows x 32 k (hi+lo), 2048 b32 words each
#pragma unroll
        for (int q = 0; q < 8; q++) {
            int idx = q*256 + tid;
            int r = idx >> 4, c = (idx & 15) * 2;
            *(uint32_t*)&Ah[r*KPCH + c] = *(const uint32_t*)&g_zh[(size_t)(m0+r)*TH_ + k0 + c];
            *(uint32_t*)&Al[r*KPCH + c] = *(const uint32_t*)&g_zl[(size_t)(m0+r)*TH_ + k0 + c];
        }
        // fill B: 64 rows x 32 k (hi+lo), 1024 b32 words each
#pragma unroll
        for (int q = 0; q < 4; q++) {
            int idx = q*256 + tid;
            int r = idx >> 4, c = (idx & 15) * 2;
            *(uint32_t*)&Bh[r*KPCH + c] = *(const uint32_t*)&g_wh[(size_t)(n0+r)*TH_ + k0 + c];
            *(uint32_t*)&Bl[r*KPCH + c] = *(const uint32_t*)&g_wl[(size_t)(n0+r)*TH_ + k0 + c];
        }
        __syncthreads();
#pragma unroll
        for (int ks = 0; ks < 2; ks++) {
            const int kk = ks * 16;
            const int abase = arow*KPCH + kk + koff;
            uint32_t ah0 = *(const uint32_t*)&Ah[abase];
            uint32_t ah1 = *(const uint32_t*)&Ah[abase + 8*KPCH];
            uint32_t ah2 = *(const uint32_t*)&Ah[abase + 8];
            uint32_t ah3 = *(const uint32_t*)&Ah[abase + 8*KPCH + 8];
            uint32_t al0 = *(const uint32_t*)&Al[abase];
            uint32_t al1 = *(const uint32_t*)&Al[abase + 8*KPCH];
            uint32_t al2 = *(const uint32_t*)&Al[abase + 8];
            uint32_t al3 = *(const uint32_t*)&Al[abase + 8*KPCH + 8];
#pragma unroll
            for (int t = 0; t < 8; t++) {
                const int bbase = (t*8 + (lane>>2))*KPCH + kk + koff;
                uint32_t bh0 = *(const uint32_t*)&Bh[bbase];
                uint32_t bh1 = *(const uint32_t*)&Bh[bbase + 8];
                uint32_t bl0 = *(const uint32_t*)&Bl[bbase];
                uint32_t bl1 = *(const uint32_t*)&Bl[bbase + 8];
                mma_bf16(acc[t], ah0, ah1, ah2, ah3, bh0, bh1);
                mma_bf16(acc[t], ah0, ah1, ah2, ah3, bl0, bl1);
                mma_bf16(acc[t], al0, al1, al2, al3, bh0, bh1);
            }
        }
        __syncthreads();
    }

    // epilogue: cols [0,128) -> h1 (bias+relu); [128,192) -> zp
    const int m  = m0 + arow;
    const int cl = (lane & 3) * 2;
    if (n0 < HID2_) {
#pragma unroll
        for (int t = 0; t < 8; t++) {
            int col = n0 + t*8 + cl;
            float b0 = __ldg(&b1v[col]), b1 = __ldg(&b1v[col+1]);
            float2 v0 = { fmaxf(acc[t][0] + b0, 0.f), fmaxf(acc[t][1] + b1, 0.f) };
            float2 v1 = { fmaxf(acc[t][2] + b0, 0.f), fmaxf(acc[t][3] + b1, 0.f) };
            *(float2*)&g_h1[(size_t)m*HID2_ + col]     = v0;
            *(float2*)&g_h1[(size_t)(m+8)*HID2_ + col] = v1;
        }
    } else {
#pragma unroll
        for (int t = 0; t < 8; t++) {
            int col = t*8 + cl;  // zp-local
            float2 v0 = { acc[t][0], acc[t][1] };
            float2 v1 = { acc[t][2], acc[t][3] };
            *(float2*)&g_zp[(size_t)m*H_ + col]     = v0;
            *(float2*)&g_zp[(size_t)(m+8)*H_ + col] = v1;
        }
    }
}

// ---------------- f32x2 GEMM (small-K chain) ----------------
template<int BM, int BN, bool RELU, bool HASBIAS, bool HASAUX, bool DOBN>
__device__ __forceinline__ void gemm_body(
    const float* __restrict__ A, const float* __restrict__ Bw,
    float* __restrict__ C, int K, int mblk,
    const float* __restrict__ bias, const float* __restrict__ aux,
    const float* __restrict__ bng, const float* __restrict__ bnb,
    const float* __restrict__ bnm, const float* __restrict__ bnv,
    char* smem)
{
    constexpr int BK = 16;
    constexpr int TXC = BN / 8;
    constexpr int TM  = 4;
    constexpr int PITCH = BM + 2;
    float2* Asd = (float2*)smem;
    float*  Bs  = (float*)(smem + BK*PITCH*sizeof(float2));

    const int tid  = threadIdx.x;
    const int lane = tid & 31, warp = tid >> 5;
    const int tx = lane % TXC;
    const int ty = warp * (32/TXC) + lane / TXC;
    const int m0 = mblk * BM;
    const int c0 = tx * 4;
    const int c1 = BN/2 + tx * 4;

    u64 acc[TM][4];
#pragma unroll
    for (int i = 0; i < TM; i++)
#pragma unroll
        for (int j = 0; j < 4; j++) acc[i][j] = 0ull;

    for (int k0 = 0; k0 < K; k0 += BK) {
#pragma unroll
        for (int q = 0; q < BM*BK/128; q++) {
            int idx = q*128 + tid;
            int k = idx & (BK-1);
            int m = idx >> 4;
            float v = A[(size_t)(m0 + m)*K + k0 + k];
            Asd[k*PITCH + m] = make_float2(v, v);
        }
#pragma unroll
        for (int q = 0; q < BK*BN/512; q++) {
            int idx4 = q*128 + tid;
            int k  = idx4 / (BN/4);
            int n4 = (idx4 % (BN/4)) * 4;
            *(float4*)&Bs[k*BN + n4] = *(const float4*)&Bw[(size_t)(k0 + k)*BN + n4];
        }
        __syncthreads();
#pragma unroll
        for (int kk = 0; kk < BK; kk++) {
            ulonglong2 a01 = *(const ulonglong2*)&Asd[kk*PITCH + ty*TM];
            ulonglong2 a23 = *(const ulonglong2*)&Asd[kk*PITCH + ty*TM + 2];
            u64 rm[TM] = {a01.x, a01.y, a23.x, a23.y};
            ulonglong2 bl = *(const ulonglong2*)&Bs[kk*BN + c0];
            ulonglong2 bh = *(const ulonglong2*)&Bs[kk*BN + c1];
            u64 rn[4] = {bl.x, bl.y, bh.x, bh.y};
#pragma unroll
            for (int i = 0; i < TM; i++)
#pragma unroll
                for (int j = 0; j < 4; j++)
                    acc[i][j] = fma2(rm[i], rn[j], acc[i][j]);
        }
        __syncthreads();
    }

#pragma unroll
    for (int i = 0; i < TM; i++) {
        int m = m0 + ty*TM + i;
#pragma unroll
        for (int g = 0; g < 2; g++) {
            int nb = g ? c1 : c0;
            float2 v0 = unpack2(acc[i][2*g]);
            float2 v1 = unpack2(acc[i][2*g+1]);
            float vv[4] = {v0.x, v0.y, v1.x, v1.y};
            float4 o;
            float* op = (float*)&o;
#pragma unroll
            for (int q = 0; q < 4; q++) {
                int n = nb + q;
                float c = vv[q];
                if (HASBIAS) c += bias[n];
                if (HASAUX)  c += aux[(size_t)m*BN + n];
                if (DOBN)    c = (c - bnm[n]) * rsqrtf(bnv[n] + BN_EPS_) * bng[n] + bnb[n];
                if (RELU)    c = fmaxf(c, 0.f);
                op[q] = c;
            }
            *(float4*)&C[(size_t)m*BN + nb] = o;
        }
    }
}

#define SMEM_BYTES (16*(64+2)*8 + 16*128*4)

template<int BM, int BN, bool RELU, bool HASBIAS, bool HASAUX, bool DOBN>
__global__ void __launch_bounds__(128) k_gemm(
    const float* __restrict__ A, const float* __restrict__ Bw,
    float* __restrict__ C, int K,
    const float* __restrict__ bias, const float* __restrict__ aux,
    const float* __restrict__ bng, const float* __restrict__ bnb,
    const float* __restrict__ bnm, const float* __restrict__ bnv)
{
    __shared__ __align__(16) char smem[SMEM_BYTES];
    gemm_body<BM,BN,RELU,HASBIAS,HASAUX,DOBN>(A, Bw, C, K, blockIdx.x,
        bias, aux, bng, bnb, bnm, bnv, smem);
}

// ---------------- K7: final stage ----------------
__global__ void __launch_bounds__(64) k_final(
    const float* __restrict__ w3,  const float* __restrict__ b3,
    const float* __restrict__ pj,
    const float* __restrict__ bng, const float* __restrict__ bnb,
    const float* __restrict__ bnm, const float* __restrict__ bnv,
    float* __restrict__ out)
{
    __shared__ float w3s[HID2_*TOUT_];
    __shared__ float pjs[H_*TOUT_];
    const int tid = threadIdx.x;
    for (int idx = tid; idx < HID2_*TOUT_; idx += 64) w3s[idx] = w3[idx];
    for (int idx = tid; idx < H_*TOUT_;    idx += 64) pjs[idx] = pj[idx];
    __syncthreads();

    const int row = blockIdx.x * 64 + tid;
    float acc[TOUT_];
#pragma unroll
    for (int o = 0; o < TOUT_; o++) acc[o] = b3[o];

    const float4* hr = (const float4*)&g_h4[(size_t)row * HID2_];
#pragma unroll 4
    for (int k4 = 0; k4 < HID2_/4; k4++) {
        float4 hv = __ldg(&hr[k4]);
        float h[4] = {hv.x, hv.y, hv.z, hv.w};
#pragma unroll
        for (int q = 0; q < 4; q++) {
            int k = k4*4 + q;
#pragma unroll
            for (int o = 0; o < TOUT_; o++)
                acc[o] = fmaf(h[q], w3s[k*TOUT_ + o], acc[o]);
        }
    }
    const float4* er = (const float4*)&g_e[(size_t)row * H_];
#pragma unroll 4
    for (int k4 = 0; k4 < H_/4; k4++) {
        float4 ev = __ldg(&er[k4]);
        float e4[4] = {ev.x, ev.y, ev.z, ev.w};
#pragma unroll
        for (int q = 0; q < 4; q++) {
            int k = k4*4 + q;
#pragma unroll
            for (int o = 0; o < TOUT_; o++)
                acc[o] = fmaf(e4[q], pjs[k*TOUT_ + o], acc[o]);
        }
    }

    const int b = row / N_, n = row % N_;
#pragma unroll
    for (int o = 0; o < TOUT_; o++) {
        float c = (acc[o] - bnm[o]) * rsqrtf(bnv[o] + BN_EPS_) * bng[o] + bnb[o];
        out[((size_t)(b*TOUT_ + o))*N_ + n] = c;
    }
}

// ---------------- host launch ----------------
extern "C" void kernel_launch(void* const* d_in, const int* in_sizes, int n_in,
                              void* d_out, int out_size)
{
    const float* x        = (const float*)d_in[0];
    const float* W1       = (const float*)d_in[1];
    const float* W2       = (const float*)d_in[2];
    const float* enc_w1   = (const float*)d_in[3];
    const float* enc_b1   = (const float*)d_in[4];
    const float* enc_w2   = (const float*)d_in[5];
    const float* enc_b2   = (const float*)d_in[6];
    const float* enc_w3   = (const float*)d_in[7];
    const float* enc_b3   = (const float*)d_in[8];
    const float* enc_proj = (const float*)d_in[9];
    const float* enc_bn_g = (const float*)d_in[10];
    const float* enc_bn_b = (const float*)d_in[11];
    const float* enc_bn_m = (const float*)d_in[12];
    const float* enc_bn_v = (const float*)d_in[13];
    const float* dec_w1   = (const float*)d_in[14];
    const float* dec_b1   = (const float*)d_in[15];
    const float* dec_w2   = (const float*)d_in[16];
    const float* dec_b2   = (const float*)d_in[17];
    const float* dec_w3   = (const float*)d_in[18];
    const float* dec_b3   = (const float*)d_in[19];
    const float* dec_proj = (const float*)d_in[20];
    const float* dec_bn_g = (const float*)d_in[21];
    const float* dec_bn_b = (const float*)d_in[22];
    const float* dec_bn_m = (const float*)d_in[23];
    const float* dec_bn_v = (const float*)d_in[24];
    float* out = (float*)d_out;

    void *ph1, *pzp, *ph2, *pe, *ph3, *ph4;
    cudaGetSymbolAddress(&ph1, g_h1);
    cudaGetSymbolAddress(&pzp, g_zp);
    cudaGetSymbolAddress(&ph2, g_h2);
    cudaGetSymbolAddress(&pe,  g_e);
    cudaGetSymbolAddress(&ph3, g_h3);
    cudaGetSymbolAddress(&ph4, g_h4);
    float* H1 = (float*)ph1;
    float* ZP = (float*)pzp;
    float* H2 = (float*)ph2;
    float* E  = (float*)pe;
    float* H3 = (float*)ph3;
    float* H4 = (float*)ph4;

    k_softmax  <<<M_/64, 64>>>(x);
    k_graph    <<<dim3(N_/128, N_/JC, B_), 128>>>(x);
    k_gfin     <<<M_/128, 128>>>();
    k_buildz   <<<(M_*TH_/4)/256, 256>>>(x, W1, W2);
    k_transpose<<<((HID2_+H_)*TH_)/256, 256>>>(enc_w1, enc_proj);

    // h1 = relu(z @ enc_w1 + b1), zp = z @ enc_proj  — mma.sync bf16x3
    k_pair_mma<<<dim3(M_/128, 3), 256>>>(enc_b1);

    const int GB128 = M_/32;
    const int GB64  = M_/64;

    // h2 = relu(h1 @ enc_w2 + b2)  (K=128, N=128)
    k_gemm<32,128,true ,true ,false,false><<<GB128,128>>>(H1, enc_w2, H2, HID2_,
        enc_b2, nullptr, nullptr, nullptr, nullptr, nullptr);
    // e = BN(h2 @ enc_w3 + b3 + zp) (K=128, N=64)
    k_gemm<64, 64,false,true ,true ,true ><<<GB64,128>>>(H2, enc_w3, E, HID2_,
        enc_b3, ZP, enc_bn_g, enc_bn_b, enc_bn_m, enc_bn_v);
    // h3 = relu(e @ dec_w1 + db1)  (K=64, N=128)
    k_gemm<32,128,true ,true ,false,false><<<GB128,128>>>(E, dec_w1, H3, H_,
        dec_b1, nullptr, nullptr, nullptr, nullptr, nullptr);
    // h4 = relu(h3 @ dec_w2 + db2) (K=128, N=128)
    k_gemm<32,128,true ,true ,false,false><<<GB128,128>>>(H3, dec_w2, H4, HID2_,
        dec_b2, nullptr, nullptr, nullptr, nullptr, nullptr);

    // out = transpose(BN(h4 @ dec_w3 + db3 + e @ dec_proj))
    k_final<<<M_/64, 64>>>(dec_w3, dec_b3, dec_proj,
                           dec_bn_g, dec_bn_b, dec_bn_m, dec_bn_v, out);
}

// round 6
// speedup vs baseline: 2.4225x; 1.0569x over previous
#include <cuda_runtime.h>
#include <cuda_bf16.h>
#include <math.h>
#include <stdint.h>

#define B_    8
#define T_    12
#define N_    1536
#define H_    64
#define TH_   768
#define HID2_ 128
#define TOUT_ 12
#define M_    (B_*N_)          // 12288
#define DELTA_   0.5f
#define ALPHA_   0.3f
#define KHOPS_   3.0f
#define KL_EPS_  1e-10f
#define BN_EPS_  1e-5f
#define DEG_MIN_ 1e-6f

typedef unsigned long long u64;

// ---------------- packed fp32x2 helpers (sm_103a FFMA2) ----------------
__device__ __forceinline__ u64 fma2(u64 a, u64 b, u64 c) {
    u64 d;
    asm("fma.rn.f32x2 %0, %1, %2, %3;" : "=l"(d) : "l"(a), "l"(b), "l"(c));
    return d;
}
__device__ __forceinline__ u64 pack2(float x, float y) {
    u64 d;
    asm("mov.b64 %0, {%1, %2};" : "=l"(d) : "f"(x), "f"(y));
    return d;
}
__device__ __forceinline__ float2 unpack2(u64 v) {
    float2 r;
    asm("mov.b64 {%0, %1}, %2;" : "=f"(r.x), "=f"(r.y) : "l"(v));
    return r;
}

// ---------------- warp mma.sync bf16 ----------------
__device__ __forceinline__ void mma_bf16(float* c,
    uint32_t a0, uint32_t a1, uint32_t a2, uint32_t a3,
    uint32_t b0, uint32_t b1)
{
    asm volatile(
        "mma.sync.aligned.m16n8k16.row.col.f32.bf16.bf16.f32 "
        "{%0,%1,%2,%3}, {%4,%5,%6,%7}, {%8,%9}, {%0,%1,%2,%3};"
        : "+f"(c[0]), "+f"(c[1]), "+f"(c[2]), "+f"(c[3])
        : "r"(a0), "r"(a1), "r"(a2), "r"(a3), "r"(b0), "r"(b1));
}

__device__ __forceinline__ void split_bf16(float v, __nv_bfloat16& h, __nv_bfloat16& l) {
    h = __float2bfloat16(v);
    l = __float2bfloat16(v - __bfloat162float(h));
}

// ---------------- device scratch ----------------
__device__ __align__(16) float g_p [M_*T_];
__device__ __align__(16) float g_lp[M_*T_];
__device__ float g_s  [M_];
__device__ float g_deg[M_];
__device__ float g_ind[M_];
__device__ __align__(16) float g_af[M_*T_];
__device__ __align__(16) float g_ab[M_*T_];
__device__ __align__(16) float g_gg[M_*T_];
__device__ __align__(16) __nv_bfloat16 g_zh[(size_t)M_*TH_];
__device__ __align__(16) __nv_bfloat16 g_zl[(size_t)M_*TH_];
__device__ __align__(16) __nv_bfloat16 g_wh[(size_t)(HID2_+H_)*TH_];  // [192 n][768 k] (enc_w1|enc_proj)
__device__ __align__(16) __nv_bfloat16 g_wl[(size_t)(HID2_+H_)*TH_];
// chain weights, transposed [n][k] bf16 hi/lo, packed segments:
// [0,16384): enc_w2 128n x 128k | [16384,24576): enc_w3 64n x 128k
// [24576,32768): dec_w1 128n x 64k | [32768,49152): dec_w2 128n x 128k
__device__ __align__(16) __nv_bfloat16 g_cwh[49152];
__device__ __align__(16) __nv_bfloat16 g_cwl[49152];
// chain activations bf16 hi/lo
__device__ __align__(16) __nv_bfloat16 g_h1h[(size_t)M_*HID2_];
__device__ __align__(16) __nv_bfloat16 g_h1l[(size_t)M_*HID2_];
__device__ __align__(16) __nv_bfloat16 g_h2h[(size_t)M_*HID2_];
__device__ __align__(16) __nv_bfloat16 g_h2l[(size_t)M_*HID2_];
__device__ __align__(16) __nv_bfloat16 g_eh [(size_t)M_*H_];
__device__ __align__(16) __nv_bfloat16 g_el [(size_t)M_*H_];
__device__ __align__(16) __nv_bfloat16 g_h3h[(size_t)M_*HID2_];
__device__ __align__(16) __nv_bfloat16 g_h3l[(size_t)M_*HID2_];
__device__ __align__(16) float g_zp[(size_t)M_*H_];
__device__ __align__(16) float g_e [(size_t)M_*H_];
__device__ __align__(16) float g_h4[(size_t)M_*HID2_];

// ---------------- K1: softmax / logp / s ----------------
__global__ void __launch_bounds__(64) k_softmax(const float* __restrict__ x) {
    int bn = blockIdx.x * 64 + threadIdx.x;
    if (bn >= M_) return;
    int b = bn / N_, n = bn % N_;
    float v[T_];
    float mx = -1e30f;
#pragma unroll
    for (int t = 0; t < T_; t++) {
        v[t] = x[((size_t)(b*T_ + t))*N_ + n];
        mx = fmaxf(mx, v[t]);
    }
    float sum = 0.f;
#pragma unroll
    for (int t = 0; t < T_; t++) { v[t] = expf(v[t] - mx); sum += v[t]; }
    float inv = 1.f / sum;
    float s = 0.f;
    size_t base = (size_t)bn * T_;
#pragma unroll
    for (int t = 0; t < T_; t++) {
        float p  = v[t] * inv;
        float lp = logf(p + KL_EPS_);
        g_p [base + t] = p;
        g_lp[base + t] = lp;
        g_af[base + t] = 0.f;
        g_ab[base + t] = 0.f;
        s = fmaf(p, lp, s);
    }
    g_s[bn] = s;
    g_deg[bn] = 0.f;
    g_ind[bn] = 0.f;
}

// ---------------- K2: graph threshold + masked aggregation ----------------
#define JC 256
__global__ void __launch_bounds__(128) k_graph(const float* __restrict__ x) {
    __shared__ __align__(16) float psh[JC*T_];
    __shared__ __align__(16) float lsh[JC*T_];
    __shared__ __align__(16) float xsh[JC*T_];
    __shared__ float ssh[JC];

    const int tid = threadIdx.x;
    const int b   = blockIdx.z;
    const int i   = blockIdx.x * 128 + tid;
    const int j0  = blockIdx.y * JC;
    const int bN  = b * N_;

    {
        size_t base = (size_t)(bN + j0) * T_;
        const float4* sp = (const float4*)(g_p  + base);
        const float4* sl = (const float4*)(g_lp + base);
#pragma unroll
        for (int q = 0; q < (JC*T_/4)/128; q++) {
            int idx = q*128 + tid;
            ((float4*)psh)[idx] = sp[idx];
            ((float4*)lsh)[idx] = sl[idx];
        }
#pragma unroll
        for (int t = 0; t < T_; t++) {
            xsh[tid*T_ + t]        = x[((size_t)(b*T_ + t))*N_ + j0 + tid];
            xsh[(tid+128)*T_ + t]  = x[((size_t)(b*T_ + t))*N_ + j0 + tid + 128];
        }
        ssh[tid]       = g_s[bN + j0 + tid];
        ssh[tid + 128] = g_s[bN + j0 + tid + 128];
    }

    u64 pi2[6], li2[6];
    {
        const ulonglong2* pp = (const ulonglong2*)(g_p  + (size_t)(bN + i)*T_);
        const ulonglong2* lp = (const ulonglong2*)(g_lp + (size_t)(bN + i)*T_);
#pragma unroll
        for (int q = 0; q < 3; q++) {
            ulonglong2 a = pp[q]; pi2[2*q] = a.x; pi2[2*q+1] = a.y;
            ulonglong2 c = lp[q]; li2[2*q] = c.x; li2[2*q+1] = c.y;
        }
    }
    const float si = g_s[bN + i];

    u64 accf2[6], accb2[6];
#pragma unroll
    for (int t = 0; t < 6; t++) { accf2[t] = 0ull; accb2[t] = 0ull; }
    float deg = 0.f, ind = 0.f;

    __syncthreads();

    for (int jj = 0; jj < JC; jj++) {
        const u64* pj2 = (const u64*)(psh + jj*T_);
        const u64* lj2 = (const u64*)(lsh + jj*T_);
        u64 d1 = 0ull, d2 = 0ull;
#pragma unroll
        for (int t = 0; t < 6; t++) {
            d1 = fma2(pi2[t], lj2[t], d1);
            d2 = fma2(pj2[t], li2[t], d2);
        }
        float2 r1 = unpack2(d1);
        float2 r2 = unpack2(d2);
        float d1s = r1.x + r1.y;
        float d2s = r2.x + r2.y;
        float mf = ((si - d1s)      < DELTA_) ? 1.f : 0.f;
        float mb = ((ssh[jj] - d2s) < DELTA_) ? 1.f : 0.f;
        deg += mf; ind += mb;
        u64 mf2 = pack2(mf, mf);
        u64 mb2 = pack2(mb, mb);
        const u64* xj2 = (const u64*)(xsh + jj*T_);
#pragma unroll
        for (int t = 0; t < 6; t++) {
            u64 xv = xj2[t];
            accf2[t] = fma2(mf2, xv, accf2[t]);
            accb2[t] = fma2(mb2, xv, accb2[t]);
        }
    }

    atomicAdd(&g_deg[bN + i], deg);
    atomicAdd(&g_ind[bN + i], ind);
    size_t obase = (size_t)(bN + i) * T_;
#pragma unroll
    for (int t = 0; t < 6; t++) {
        float2 f = unpack2(accf2[t]);
        float2 g = unpack2(accb2[t]);
        atomicAdd(&g_af[obase + 2*t    ], f.x);
        atomicAdd(&g_af[obase + 2*t + 1], f.y);
        atomicAdd(&g_ab[obase + 2*t    ], g.x);
        atomicAdd(&g_ab[obase + 2*t + 1], g.y);
    }
}

// ---------------- K2b: finalize message ----------------
__global__ void k_gfin() {
    int row = blockIdx.x * 128 + threadIdx.x;
    if (row >= M_) return;
    float rf = (KHOPS_ * ALPHA_)        * __frcp_rn(fmaxf(g_deg[row], DEG_MIN_));
    float rb = (KHOPS_ * (1.f-ALPHA_))  * __frcp_rn(fmaxf(g_ind[row], DEG_MIN_));
    size_t base = (size_t)row * T_;
#pragma unroll
    for (int t = 0; t < T_; t++)
        g_gg[base + t] = rf * g_af[base + t] + rb * g_ab[base + t];
}

// ---------------- K3: build z = relu(x*W1 + g*W2), split to bf16 hi/lo ----------------
__global__ void __launch_bounds__(256) k_buildz(const float* __restrict__ x,
                                                const float* __restrict__ W1,
                                                const float* __restrict__ W2) {
    int idx4 = blockIdx.x * 256 + threadIdx.x;
    if (idx4 >= M_*TH_/4) return;
    int row = idx4 / (TH_/4);
    int c4  = idx4 % (TH_/4);
    int t   = c4 >> 4;
    int h4  = (c4 & 15) * 4;
    int b = row / N_, n = row % N_;
    float xv = x[((size_t)(b*T_ + t))*N_ + n];
    float gg = g_gg[row*T_ + t];
    float4 w1 = *(const float4*)&W1[h4];
    float4 w2 = *(const float4*)&W2[h4];
    float v0 = fmaxf(fmaf(xv, w1.x, gg * w2.x), 0.f);
    float v1 = fmaxf(fmaf(xv, w1.y, gg * w2.y), 0.f);
    float v2 = fmaxf(fmaf(xv, w1.z, gg * w2.z), 0.f);
    float v3 = fmaxf(fmaf(xv, w1.w, gg * w2.w), 0.f);
    __nv_bfloat16 h0, h1, h2, h3, l0, l1, l2, l3;
    split_bf16(v0, h0, l0); split_bf16(v1, h1, l1);
    split_bf16(v2, h2, l2); split_bf16(v3, h3, l3);
    size_t o = (size_t)idx4 * 4;
    *(__nv_bfloat162*)&g_zh[o]   = __nv_bfloat162{h0, h1};
    *(__nv_bfloat162*)&g_zh[o+2] = __nv_bfloat162{h2, h3};
    *(__nv_bfloat162*)&g_zl[o]   = __nv_bfloat162{l0, l1};
    *(__nv_bfloat162*)&g_zl[o+2] = __nv_bfloat162{l2, l3};
}

// ---------------- K3b: transpose+split enc_w1|enc_proj to [192 n][768 k] ----------------
__global__ void __launch_bounds__(256) k_transpose(const float* __restrict__ w1,
                                                   const float* __restrict__ proj) {
    int idx = blockIdx.x * 256 + threadIdx.x;
    if (idx >= (HID2_+H_)*TH_) return;
    int n = idx / TH_, k = idx % TH_;
    float v = (n < HID2_) ? w1[(size_t)k*HID2_ + n] : proj[(size_t)k*H_ + (n - HID2_)];
    __nv_bfloat16 h, l;
    split_bf16(v, h, l);
    g_wh[idx] = h;
    g_wl[idx] = l;
}

// ---------------- K3c: transpose+split chain weights ----------------
__global__ void __launch_bounds__(256) k_prepw(const float* __restrict__ w2,
                                               const float* __restrict__ w3,
                                               const float* __restrict__ dw1,
                                               const float* __restrict__ dw2) {
    int idx = blockIdx.x * 256 + threadIdx.x;
    if (idx >= 49152) return;
    float v;
    if (idx < 16384)      { int j = idx;         int n = j/128, k = j%128; v = w2 [(size_t)k*HID2_ + n]; }
    else if (idx < 24576) { int j = idx - 16384; int n = j/128, k = j%128; v = w3 [(size_t)k*H_    + n]; }
    else if (idx < 32768) { int j = idx - 24576; int n = j/64,  k = j%64;  v = dw1[(size_t)k*HID2_ + n]; }
    else                  { int j = idx - 32768; int n = j/128, k = j%128; v = dw2[(size_t)k*HID2_ + n]; }
    __nv_bfloat16 h, l;
    split_bf16(v, h, l);
    g_cwh[idx] = h;
    g_cwl[idx] = l;
}

// ---------------- K4: mma.sync bf16x3 fused GEMM: h1(hi/lo) = relu(Z@w1+b1), zp = Z@proj ----------------
#define KPCH 40
__global__ void __launch_bounds__(256) k_pair_mma(const float* __restrict__ b1v) {
    __shared__ __align__(16) __nv_bfloat16 Ah[128*KPCH];
    __shared__ __align__(16) __nv_bfloat16 Al[128*KPCH];
    __shared__ __align__(16) __nv_bfloat16 Bh[64*KPCH];
    __shared__ __align__(16) __nv_bfloat16 Bl[64*KPCH];

    const int tid  = threadIdx.x;
    const int w    = tid >> 5, lane = tid & 31;
    const int m0   = blockIdx.x * 128;
    const int n0   = blockIdx.y * 64;

    float acc[8][4];
#pragma unroll
    for (int t = 0; t < 8; t++)
#pragma unroll
        for (int j = 0; j < 4; j++) acc[t][j] = 0.f;

    const int arow = w*16 + (lane >> 2);
    const int koff = (lane & 3) * 2;

    for (int k0 = 0; k0 < TH_; k0 += 32) {
#pragma unroll
        for (int q = 0; q < 8; q++) {
            int idx = q*256 + tid;
            int r = idx >> 4, c = (idx & 15) * 2;
            *(uint32_t*)&Ah[r*KPCH + c] = *(const uint32_t*)&g_zh[(size_t)(m0+r)*TH_ + k0 + c];
            *(uint32_t*)&Al[r*KPCH + c] = *(const uint32_t*)&g_zl[(size_t)(m0+r)*TH_ + k0 + c];
        }
#pragma unroll
        for (int q = 0; q < 4; q++) {
            int idx = q*256 + tid;
            int r = idx >> 4, c = (idx & 15) * 2;
            *(uint32_t*)&Bh[r*KPCH + c] = *(const uint32_t*)&g_wh[(size_t)(n0+r)*TH_ + k0 + c];
            *(uint32_t*)&Bl[r*KPCH + c] = *(const uint32_t*)&g_wl[(size_t)(n0+r)*TH_ + k0 + c];
        }
        __syncthreads();
#pragma unroll
        for (int ks = 0; ks < 2; ks++) {
            const int kk = ks * 16;
            const int abase = arow*KPCH + kk + koff;
            uint32_t ah0 = *(const uint32_t*)&Ah[abase];
            uint32_t ah1 = *(const uint32_t*)&Ah[abase + 8*KPCH];
            uint32_t ah2 = *(const uint32_t*)&Ah[abase + 8];
            uint32_t ah3 = *(const uint32_t*)&Ah[abase + 8*KPCH + 8];
            uint32_t al0 = *(const uint32_t*)&Al[abase];
            uint32_t al1 = *(const uint32_t*)&Al[abase + 8*KPCH];
            uint32_t al2 = *(const uint32_t*)&Al[abase + 8];
            uint32_t al3 = *(const uint32_t*)&Al[abase + 8*KPCH + 8];
#pragma unroll
            for (int t = 0; t < 8; t++) {
                const int bbase = (t*8 + (lane>>2))*KPCH + kk + koff;
                uint32_t bh0 = *(const uint32_t*)&Bh[bbase];
                uint32_t bh1 = *(const uint32_t*)&Bh[bbase + 8];
                uint32_t bl0 = *(const uint32_t*)&Bl[bbase];
                uint32_t bl1 = *(const uint32_t*)&Bl[bbase + 8];
                mma_bf16(acc[t], ah0, ah1, ah2, ah3, bh0, bh1);
                mma_bf16(acc[t], ah0, ah1, ah2, ah3, bl0, bl1);
                mma_bf16(acc[t], al0, al1, al2, al3, bh0, bh1);
            }
        }
        __syncthreads();
    }

    const int m  = m0 + arow;
    const int cl = (lane & 3) * 2;
    if (n0 < HID2_) {
#pragma unroll
        for (int t = 0; t < 8; t++) {
            int col = n0 + t*8 + cl;
            float b0 = __ldg(&b1v[col]), b1 = __ldg(&b1v[col+1]);
            float v00 = fmaxf(acc[t][0] + b0, 0.f), v01 = fmaxf(acc[t][1] + b1, 0.f);
            float v10 = fmaxf(acc[t][2] + b0, 0.f), v11 = fmaxf(acc[t][3] + b1, 0.f);
            __nv_bfloat16 h0,h1,h2,h3,l0,l1,l2,l3;
            split_bf16(v00,h0,l0); split_bf16(v01,h1,l1);
            split_bf16(v10,h2,l2); split_bf16(v11,h3,l3);
            *(__nv_bfloat162*)&g_h1h[(size_t)m*HID2_ + col]     = __nv_bfloat162{h0,h1};
            *(__nv_bfloat162*)&g_h1l[(size_t)m*HID2_ + col]     = __nv_bfloat162{l0,l1};
            *(__nv_bfloat162*)&g_h1h[(size_t)(m+8)*HID2_ + col] = __nv_bfloat162{h2,h3};
            *(__nv_bfloat162*)&g_h1l[(size_t)(m+8)*HID2_ + col] = __nv_bfloat162{l2,l3};
        }
    } else {
#pragma unroll
        for (int t = 0; t < 8; t++) {
            int col = t*8 + cl;
            float2 v0 = { acc[t][0], acc[t][1] };
            float2 v1 = { acc[t][2], acc[t][3] };
            *(float2*)&g_zp[(size_t)m*H_ + col]     = v0;
            *(float2*)&g_zp[(size_t)(m+8)*H_ + col] = v1;
        }
    }
}

// ---------------- K5: generic bf16x3 mma chain GEMM ----------------
// A: [M, KD] bf16 hi/lo. B: [*, KD] bf16 hi/lo rows (n0+r). 256 thr, M-tile 128, N 64/blockIdx.y.
template<int KD, bool RELU, bool HASAUX, bool DOBN, bool OUTF32, bool OUTHILO>
__global__ void __launch_bounds__(256) k_mma(
    const __nv_bfloat16* __restrict__ Ahp, const __nv_bfloat16* __restrict__ Alp,
    const __nv_bfloat16* __restrict__ Bhp, const __nv_bfloat16* __restrict__ Blp,
    const float* __restrict__ bias,
    const float* __restrict__ aux, int auxN,
    const float* __restrict__ bng, const float* __restrict__ bnb,
    const float* __restrict__ bnm, const float* __restrict__ bnv,
    float* __restrict__ oF, int oFN,
    __nv_bfloat16* __restrict__ oH, __nv_bfloat16* __restrict__ oL, int oN)
{
    __shared__ __align__(16) __nv_bfloat16 Ah[128*KPCH];
    __shared__ __align__(16) __nv_bfloat16 Al[128*KPCH];
    __shared__ __align__(16) __nv_bfloat16 Bh[64*KPCH];
    __shared__ __align__(16) __nv_bfloat16 Bl[64*KPCH];

    const int tid  = threadIdx.x;
    const int w    = tid >> 5, lane = tid & 31;
    const int m0   = blockIdx.x * 128;
    const int n0   = blockIdx.y * 64;

    float acc[8][4];
#pragma unroll
    for (int t = 0; t < 8; t++)
#pragma unroll
        for (int j = 0; j < 4; j++) acc[t][j] = 0.f;

    const int arow = w*16 + (lane >> 2);
    const int koff = (lane & 3) * 2;

#pragma unroll
    for (int k0 = 0; k0 < KD; k0 += 32) {
#pragma unroll
        for (int q = 0; q < 8; q++) {
            int idx = q*256 + tid;
            int r = idx >> 4, c = (idx & 15) * 2;
            *(uint32_t*)&Ah[r*KPCH + c] = *(const uint32_t*)&Ahp[(size_t)(m0+r)*KD + k0 + c];
            *(uint32_t*)&Al[r*KPCH + c] = *(const uint32_t*)&Alp[(size_t)(m0+r)*KD + k0 + c];
        }
#pragma unroll
        for (int q = 0; q < 4; q++) {
            int idx = q*256 + tid;
            int r = idx >> 4, c = (idx & 15) * 2;
            *(uint32_t*)&Bh[r*KPCH + c] = *(const uint32_t*)&Bhp[(size_t)(n0+r)*KD + k0 + c];
            *(uint32_t*)&Bl[r*KPCH + c] = *(const uint32_t*)&Blp[(size_t)(n0+r)*KD + k0 + c];
        }
        __syncthreads();
#pragma unroll
        for (int ks = 0; ks < 2; ks++) {
            const int kk = ks * 16;
            const int abase = arow*KPCH + kk + koff;
            uint32_t ah0 = *(const uint32_t*)&Ah[abase];
            uint32_t ah1 = *(const uint32_t*)&Ah[abase + 8*KPCH];
            uint32_t ah2 = *(const uint32_t*)&Ah[abase + 8];
            uint32_t ah3 = *(const uint32_t*)&Ah[abase + 8*KPCH + 8];
            uint32_t al0 = *(const uint32_t*)&Al[abase];
            uint32_t al1 = *(const uint32_t*)&Al[abase + 8*KPCH];
            uint32_t al2 = *(const uint32_t*)&Al[abase + 8];
            uint32_t al3 = *(const uint32_t*)&Al[abase + 8*KPCH + 8];
#pragma unroll
            for (int t = 0; t < 8; t++) {
                const int bbase = (t*8 + (lane>>2))*KPCH + kk + koff;
                uint32_t bh0 = *(const uint32_t*)&Bh[bbase];
                uint32_t bh1 = *(const uint32_t*)&Bh[bbase + 8];
                uint32_t bl0 = *(const uint32_t*)&Bl[bbase];
                uint32_t bl1 = *(const uint32_t*)&Bl[bbase + 8];
                mma_bf16(acc[t], ah0, ah1, ah2, ah3, bh0, bh1);
                mma_bf16(acc[t], ah0, ah1, ah2, ah3, bl0, bl1);
                mma_bf16(acc[t], al0, al1, al2, al3, bh0, bh1);
            }
        }
        __syncthreads();
    }

    const int m  = m0 + arow;
    const int cl = (lane & 3) * 2;
#pragma unroll
    for (int t = 0; t < 8; t++) {
        int col = n0 + t*8 + cl;
        float b0 = __ldg(&bias[col]), b1 = __ldg(&bias[col+1]);
        float v[4] = { acc[t][0] + b0, acc[t][1] + b1, acc[t][2] + b0, acc[t][3] + b1 };
        if (HASAUX) {
            v[0] += aux[(size_t)m*auxN + col];
            v[1] += aux[(size_t)m*auxN + col + 1];
            v[2] += aux[(size_t)(m+8)*auxN + col];
            v[3] += aux[(size_t)(m+8)*auxN + col + 1];
        }
        if (DOBN) {
            float s0 = rsqrtf(__ldg(&bnv[col])   + BN_EPS_) * __ldg(&bng[col]);
            float s1 = rsqrtf(__ldg(&bnv[col+1]) + BN_EPS_) * __ldg(&bng[col+1]);
            float m0v = __ldg(&bnm[col]), m1v = __ldg(&bnm[col+1]);
            float a0 = __ldg(&bnb[col]),  a1 = __ldg(&bnb[col+1]);
            v[0] = (v[0] - m0v) * s0 + a0;
            v[1] = (v[1] - m1v) * s1 + a1;
            v[2] = (v[2] - m0v) * s0 + a0;
            v[3] = (v[3] - m1v) * s1 + a1;
        }
        if (RELU) {
#pragma unroll
            for (int q = 0; q < 4; q++) v[q] = fmaxf(v[q], 0.f);
        }
        if (OUTF32) {
            *(float2*)&oF[(size_t)m*oFN + col]     = make_float2(v[0], v[1]);
            *(float2*)&oF[(size_t)(m+8)*oFN + col] = make_float2(v[2], v[3]);
        }
        if (OUTHILO) {
            __nv_bfloat16 h0,h1,h2,h3,l0,l1,l2,l3;
            split_bf16(v[0],h0,l0); split_bf16(v[1],h1,l1);
            split_bf16(v[2],h2,l2); split_bf16(v[3],h3,l3);
            *(__nv_bfloat162*)&oH[(size_t)m*oN + col]     = __nv_bfloat162{h0,h1};
            *(__nv_bfloat162*)&oL[(size_t)m*oN + col]     = __nv_bfloat162{l0,l1};
            *(__nv_bfloat162*)&oH[(size_t)(m+8)*oN + col] = __nv_bfloat162{h2,h3};
            *(__nv_bfloat162*)&oL[(size_t)(m+8)*oN + col] = __nv_bfloat162{l2,l3};
        }
    }
}

// ---------------- K7: final stage, N=12, fused dual-GEMM + BN + transpose ----------------
__global__ void __launch_bounds__(64) k_final(
    const float* __restrict__ w3,  const float* __restrict__ b3,
    const float* __restrict__ pj,
    const float* __restrict__ bng, const float* __restrict__ bnb,
    const float* __restrict__ bnm, const float* __restrict__ bnv,
    float* __restrict__ out)
{
    __shared__ float w3s[HID2_*TOUT_];
    __shared__ float pjs[H_*TOUT_];
    const int tid = threadIdx.x;
    for (int idx = tid; idx < HID2_*TOUT_; idx += 64) w3s[idx] = w3[idx];
    for (int idx = tid; idx < H_*TOUT_;    idx += 64) pjs[idx] = pj[idx];
    __syncthreads();

    const int row = blockIdx.x * 64 + tid;
    float acc[TOUT_];
#pragma unroll
    for (int o = 0; o < TOUT_; o++) acc[o] = b3[o];

    const float4* hr = (const float4*)&g_h4[(size_t)row * HID2_];
#pragma unroll 4
    for (int k4 = 0; k4 < HID2_/4; k4++) {
        float4 hv = __ldg(&hr[k4]);
        float h[4] = {hv.x, hv.y, hv.z, hv.w};
#pragma unroll
        for (int q = 0; q < 4; q++) {
            int k = k4*4 + q;
#pragma unroll
            for (int o = 0; o < TOUT_; o++)
                acc[o] = fmaf(h[q], w3s[k*TOUT_ + o], acc[o]);
        }
    }
    const float4* er = (const float4*)&g_e[(size_t)row * H_];
#pragma unroll 4
    for (int k4 = 0; k4 < H_/4; k4++) {
        float4 ev = __ldg(&er[k4]);
        float e4[4] = {ev.x, ev.y, ev.z, ev.w};
#pragma unroll
        for (int q = 0; q < 4; q++) {
            int k = k4*4 + q;
#pragma unroll
            for (int o = 0; o < TOUT_; o++)
                acc[o] = fmaf(e4[q], pjs[k*TOUT_ + o], acc[o]);
        }
    }

    const int b = row / N_, n = row % N_;
#pragma unroll
    for (int o = 0; o < TOUT_; o++) {
        float c = (acc[o] - bnm[o]) * rsqrtf(bnv[o] + BN_EPS_) * bng[o] + bnb[o];
        out[((size_t)(b*TOUT_ + o))*N_ + n] = c;
    }
}

// ---------------- host launch ----------------
extern "C" void kernel_launch(void* const* d_in, const int* in_sizes, int n_in,
                              void* d_out, int out_size)
{
    const float* x        = (const float*)d_in[0];
    const float* W1       = (const float*)d_in[1];
    const float* W2       = (const float*)d_in[2];
    const float* enc_w1   = (const float*)d_in[3];
    const float* enc_b1   = (const float*)d_in[4];
    const float* enc_w2   = (const float*)d_in[5];
    const float* enc_b2   = (const float*)d_in[6];
    const float* enc_w3   = (const float*)d_in[7];
    const float* enc_b3   = (const float*)d_in[8];
    const float* enc_proj = (const float*)d_in[9];
    const float* enc_bn_g = (const float*)d_in[10];
    const float* enc_bn_b = (const float*)d_in[11];
    const float* enc_bn_m = (const float*)d_in[12];
    const float* enc_bn_v = (const float*)d_in[13];
    const float* dec_w1   = (const float*)d_in[14];
    const float* dec_b1   = (const float*)d_in[15];
    const float* dec_w2   = (const float*)d_in[16];
    const float* dec_b2   = (const float*)d_in[17];
    const float* dec_w3   = (const float*)d_in[18];
    const float* dec_b3   = (const float*)d_in[19];
    const float* dec_proj = (const float*)d_in[20];
    const float* dec_bn_g = (const float*)d_in[21];
    const float* dec_bn_b = (const float*)d_in[22];
    const float* dec_bn_m = (const float*)d_in[23];
    const float* dec_bn_v = (const float*)d_in[24];
    float* out = (float*)d_out;

    void *pzp, *pe, *ph4, *ph1h, *ph1l, *ph2h, *ph2l, *peh, *pel, *ph3h, *ph3l, *pcwh, *pcwl;
    cudaGetSymbolAddress(&pzp,  g_zp);
    cudaGetSymbolAddress(&pe,   g_e);
    cudaGetSymbolAddress(&ph4,  g_h4);
    cudaGetSymbolAddress(&ph1h, g_h1h);
    cudaGetSymbolAddress(&ph1l, g_h1l);
    cudaGetSymbolAddress(&ph2h, g_h2h);
    cudaGetSymbolAddress(&ph2l, g_h2l);
    cudaGetSymbolAddress(&peh,  g_eh);
    cudaGetSymbolAddress(&pel,  g_el);
    cudaGetSymbolAddress(&ph3h, g_h3h);
    cudaGetSymbolAddress(&ph3l, g_h3l);
    cudaGetSymbolAddress(&pcwh, g_cwh);
    cudaGetSymbolAddress(&pcwl, g_cwl);
    float* ZP = (float*)pzp;
    float* E  = (float*)pe;
    float* H4 = (float*)ph4;
    __nv_bfloat16* H1h = (__nv_bfloat16*)ph1h;
    __nv_bfloat16* H1l = (__nv_bfloat16*)ph1l;
    __nv_bfloat16* H2h = (__nv_bfloat16*)ph2h;
    __nv_bfloat16* H2l = (__nv_bfloat16*)ph2l;
    __nv_bfloat16* Eh  = (__nv_bfloat16*)peh;
    __nv_bfloat16* El  = (__nv_bfloat16*)pel;
    __nv_bfloat16* H3h = (__nv_bfloat16*)ph3h;
    __nv_bfloat16* H3l = (__nv_bfloat16*)ph3l;
    __nv_bfloat16* CWh = (__nv_bfloat16*)pcwh;
    __nv_bfloat16* CWl = (__nv_bfloat16*)pcwl;

    k_softmax  <<<M_/64, 64>>>(x);
    k_graph    <<<dim3(N_/128, N_/JC, B_), 128>>>(x);
    k_gfin     <<<M_/128, 128>>>();
    k_buildz   <<<(M_*TH_/4)/256, 256>>>(x, W1, W2);
    k_transpose<<<((HID2_+H_)*TH_)/256, 256>>>(enc_w1, enc_proj);
    k_prepw    <<<192, 256>>>(enc_w2, enc_w3, dec_w1, dec_w2);

    // h1(hi/lo) = relu(z @ enc_w1 + b1), zp = z @ enc_proj
    k_pair_mma<<<dim3(M_/128, 3), 256>>>(enc_b1);

    // h2(hi/lo) = relu(h1 @ enc_w2 + b2)   K=128, N=128
    k_mma<128,true ,false,false,false,true><<<dim3(M_/128, 2), 256>>>(
        H1h, H1l, CWh, CWl, enc_b2,
        nullptr, 0, nullptr, nullptr, nullptr, nullptr,
        nullptr, 0, H2h, H2l, HID2_);

    // e = BN(h2 @ enc_w3 + b3 + zp)        K=128, N=64 -> fp32 + hi/lo
    k_mma<128,false,true ,true ,true ,true><<<dim3(M_/128, 1), 256>>>(
        H2h, H2l, CWh + 16384, CWl + 16384, enc_b3,
        ZP, H_, enc_bn_g, enc_bn_b, enc_bn_m, enc_bn_v,
        E, H_, Eh, El, H_);

    // h3(hi/lo) = relu(e @ dec_w1 + db1)   K=64, N=128
    k_mma< 64,true ,false,false,false,true><<<dim3(M_/128, 2), 256>>>(
        Eh, El, CWh + 24576, CWl + 24576, dec_b1,
        nullptr, 0, nullptr, nullptr, nullptr, nullptr,
        nullptr, 0, H3h, H3l, HID2_);

    // h4 = relu(h3 @ dec_w2 + db2)         K=128, N=128 -> fp32
    k_mma<128,true ,false,false,true ,false><<<dim3(M_/128, 2), 256>>>(
        H3h, H3l, CWh + 32768, CWl + 32768, dec_b2,
        nullptr, 0, nullptr, nullptr, nullptr, nullptr,
        H4, HID2_, nullptr, nullptr, HID2_);

    // out = transpose(BN(h4 @ dec_w3 + db3 + e @ dec_proj))
    k_final<<<M_/64, 64>>>(dec_w3, dec_b3, dec_proj,
                           dec_bn_g, dec_bn_b, dec_bn_m, dec_bn_v, out);
}

// round 7
// speedup vs baseline: 2.4852x; 1.0259x over previous
#include <cuda_runtime.h>
#include <cuda_bf16.h>
#include <math.h>
#include <stdint.h>

#define B_    8
#define T_    12
#define N_    1536
#define H_    64
#define TH_   768
#define HID2_ 128
#define TOUT_ 12
#define M_    (B_*N_)          // 12288
#define DELTA_   0.5f
#define ALPHA_   0.3f
#define KHOPS_   3.0f
#define KL_EPS_  1e-10f
#define BN_EPS_  1e-5f
#define DEG_MIN_ 1e-6f

typedef unsigned long long u64;

// ---------------- packed fp32x2 helpers (sm_103a FFMA2) ----------------
__device__ __forceinline__ u64 fma2(u64 a, u64 b, u64 c) {
    u64 d;
    asm("fma.rn.f32x2 %0, %1, %2, %3;" : "=l"(d) : "l"(a), "l"(b), "l"(c));
    return d;
}
__device__ __forceinline__ u64 pack2(float x, float y) {
    u64 d;
    asm("mov.b64 %0, {%1, %2};" : "=l"(d) : "f"(x), "f"(y));
    return d;
}
__device__ __forceinline__ float2 unpack2(u64 v) {
    float2 r;
    asm("mov.b64 {%0, %1}, %2;" : "=f"(r.x), "=f"(r.y) : "l"(v));
    return r;
}

// ---------------- warp mma.sync bf16 + ldmatrix ----------------
__device__ __forceinline__ void mma_bf16(float* c,
    uint32_t a0, uint32_t a1, uint32_t a2, uint32_t a3,
    uint32_t b0, uint32_t b1)
{
    asm volatile(
        "mma.sync.aligned.m16n8k16.row.col.f32.bf16.bf16.f32 "
        "{%0,%1,%2,%3}, {%4,%5,%6,%7}, {%8,%9}, {%0,%1,%2,%3};"
        : "+f"(c[0]), "+f"(c[1]), "+f"(c[2]), "+f"(c[3])
        : "r"(a0), "r"(a1), "r"(a2), "r"(a3), "r"(b0), "r"(b1));
}
__device__ __forceinline__ void ldsm_x4(uint32_t& r0, uint32_t& r1,
                                        uint32_t& r2, uint32_t& r3, uint32_t addr)
{
    asm volatile("ldmatrix.sync.aligned.m8n8.x4.shared.b16 {%0,%1,%2,%3}, [%4];"
        : "=r"(r0), "=r"(r1), "=r"(r2), "=r"(r3) : "r"(addr));
}
__device__ __forceinline__ uint32_t s2u(const void* p) {
    uint32_t a;
    asm("{ .reg .u64 t; cvta.to.shared.u64 t, %1; cvt.u32.u64 %0, t; }" : "=r"(a) : "l"(p));
    return a;
}
__device__ __forceinline__ void split_bf16(float v, __nv_bfloat16& h, __nv_bfloat16& l) {
    h = __float2bfloat16(v);
    l = __float2bfloat16(v - __bfloat162float(h));
}

#define KPCH 40   // smem pitch (bf16); 8 ldmatrix rows at 80B stride are bank-conflict-free

// shared bf16x3 ldmatrix inner step over one 32-k smem tile (A 128 rows, B 64 rows)
__device__ __forceinline__ void mma_tile(float acc[8][4],
    uint32_t aAh, uint32_t aAl, uint32_t aBh, uint32_t aBl,
    int laneA_off, int laneB_off)
{
#pragma unroll
    for (int ks = 0; ks < 2; ks++) {
        uint32_t ah[4], al[4];
        ldsm_x4(ah[0],ah[1],ah[2],ah[3], aAh + laneA_off + ks*32);
        ldsm_x4(al[0],al[1],al[2],al[3], aAl + laneA_off + ks*32);
#pragma unroll
        for (int t2 = 0; t2 < 4; t2++) {
            uint32_t bh[4], bl[4];
            ldsm_x4(bh[0],bh[1],bh[2],bh[3], aBh + laneB_off + t2*(16*KPCH*2) + ks*32);
            ldsm_x4(bl[0],bl[1],bl[2],bl[3], aBl + laneB_off + t2*(16*KPCH*2) + ks*32);
            mma_bf16(acc[2*t2],   ah[0],ah[1],ah[2],ah[3], bh[0],bh[1]);
            mma_bf16(acc[2*t2],   ah[0],ah[1],ah[2],ah[3], bl[0],bl[1]);
            mma_bf16(acc[2*t2],   al[0],al[1],al[2],al[3], bh[0],bh[1]);
            mma_bf16(acc[2*t2+1], ah[0],ah[1],ah[2],ah[3], bh[2],bh[3]);
            mma_bf16(acc[2*t2+1], ah[0],ah[1],ah[2],ah[3], bl[2],bl[3]);
            mma_bf16(acc[2*t2+1], al[0],al[1],al[2],al[3], bh[2],bh[3]);
        }
    }
}

// ---------------- device scratch ----------------
__device__ __align__(16) float g_p [M_*T_];
__device__ __align__(16) float g_lp[M_*T_];
__device__ float g_s  [M_];
__device__ float g_deg[M_];
__device__ float g_ind[M_];
__device__ __align__(16) float g_af[M_*T_];
__device__ __align__(16) float g_ab[M_*T_];
__device__ __align__(16) __nv_bfloat16 g_zh[(size_t)M_*TH_];
__device__ __align__(16) __nv_bfloat16 g_zl[(size_t)M_*TH_];
__device__ __align__(16) __nv_bfloat16 g_wh[(size_t)(HID2_+H_)*TH_];
__device__ __align__(16) __nv_bfloat16 g_wl[(size_t)(HID2_+H_)*TH_];
// chain weights [n][k] bf16 hi/lo: enc_w2@0 (16384) | enc_w3@16384 (8192) | dec_w1@24576 (8192) | dec_w2@32768 (16384)
__device__ __align__(16) __nv_bfloat16 g_cwh[49152];
__device__ __align__(16) __nv_bfloat16 g_cwl[49152];
__device__ __align__(16) __nv_bfloat16 g_h1h[(size_t)M_*HID2_];
__device__ __align__(16) __nv_bfloat16 g_h1l[(size_t)M_*HID2_];
__device__ __align__(16) __nv_bfloat16 g_h2h[(size_t)M_*HID2_];
__device__ __align__(16) __nv_bfloat16 g_h2l[(size_t)M_*HID2_];
__device__ __align__(16) __nv_bfloat16 g_eh [(size_t)M_*H_];
__device__ __align__(16) __nv_bfloat16 g_el [(size_t)M_*H_];
__device__ __align__(16) __nv_bfloat16 g_h3h[(size_t)M_*HID2_];
__device__ __align__(16) __nv_bfloat16 g_h3l[(size_t)M_*HID2_];
__device__ __align__(16) float g_zp[(size_t)M_*H_];
__device__ __align__(16) float g_e [(size_t)M_*H_];
__device__ __align__(16) float g_h4[(size_t)M_*HID2_];

// ---------------- K1: softmax / logp / s ----------------
__global__ void __launch_bounds__(64) k_softmax(const float* __restrict__ x) {
    int bn = blockIdx.x * 64 + threadIdx.x;
    if (bn >= M_) return;
    int b = bn / N_, n = bn % N_;
    float v[T_];
    float mx = -1e30f;
#pragma unroll
    for (int t = 0; t < T_; t++) {
        v[t] = x[((size_t)(b*T_ + t))*N_ + n];
        mx = fmaxf(mx, v[t]);
    }
    float sum = 0.f;
#pragma unroll
    for (int t = 0; t < T_; t++) { v[t] = expf(v[t] - mx); sum += v[t]; }
    float inv = 1.f / sum;
    float s = 0.f;
    size_t base = (size_t)bn * T_;
#pragma unroll
    for (int t = 0; t < T_; t++) {
        float p  = v[t] * inv;
        float lp = logf(p + KL_EPS_);
        g_p [base + t] = p;
        g_lp[base + t] = lp;
        g_af[base + t] = 0.f;
        g_ab[base + t] = 0.f;
        s = fmaf(p, lp, s);
    }
    g_s[bn] = s;
    g_deg[bn] = 0.f;
    g_ind[bn] = 0.f;
}

// ---------------- K2: graph threshold + masked aggregation ----------------
#define JC 256
__global__ void __launch_bounds__(128) k_graph(const float* __restrict__ x) {
    __shared__ __align__(16) float psh[JC*T_];
    __shared__ __align__(16) float lsh[JC*T_];
    __shared__ __align__(16) float xsh[JC*T_];
    __shared__ float ssh[JC];

    const int tid = threadIdx.x;
    const int b   = blockIdx.z;
    const int i   = blockIdx.x * 128 + tid;
    const int j0  = blockIdx.y * JC;
    const int bN  = b * N_;

    {
        size_t base = (size_t)(bN + j0) * T_;
        const float4* sp = (const float4*)(g_p  + base);
        const float4* sl = (const float4*)(g_lp + base);
#pragma unroll
        for (int q = 0; q < (JC*T_/4)/128; q++) {
            int idx = q*128 + tid;
            ((float4*)psh)[idx] = sp[idx];
            ((float4*)lsh)[idx] = sl[idx];
        }
#pragma unroll
        for (int t = 0; t < T_; t++) {
            xsh[tid*T_ + t]        = x[((size_t)(b*T_ + t))*N_ + j0 + tid];
            xsh[(tid+128)*T_ + t]  = x[((size_t)(b*T_ + t))*N_ + j0 + tid + 128];
        }
        ssh[tid]       = g_s[bN + j0 + tid];
        ssh[tid + 128] = g_s[bN + j0 + tid + 128];
    }

    u64 pi2[6], li2[6];
    {
        const ulonglong2* pp = (const ulonglong2*)(g_p  + (size_t)(bN + i)*T_);
        const ulonglong2* lp = (const ulonglong2*)(g_lp + (size_t)(bN + i)*T_);
#pragma unroll
        for (int q = 0; q < 3; q++) {
            ulonglong2 a = pp[q]; pi2[2*q] = a.x; pi2[2*q+1] = a.y;
            ulonglong2 c = lp[q]; li2[2*q] = c.x; li2[2*q+1] = c.y;
        }
    }
    const float si = g_s[bN + i];

    u64 accf2[6], accb2[6];
#pragma unroll
    for (int t = 0; t < 6; t++) { accf2[t] = 0ull; accb2[t] = 0ull; }
    float deg = 0.f, ind = 0.f;

    __syncthreads();

    for (int jj = 0; jj < JC; jj++) {
        const u64* pj2 = (const u64*)(psh + jj*T_);
        const u64* lj2 = (const u64*)(lsh + jj*T_);
        u64 d1 = 0ull, d2 = 0ull;
#pragma unroll
        for (int t = 0; t < 6; t++) {
            d1 = fma2(pi2[t], lj2[t], d1);
            d2 = fma2(pj2[t], li2[t], d2);
        }
        float2 r1 = unpack2(d1);
        float2 r2 = unpack2(d2);
        float d1s = r1.x + r1.y;
        float d2s = r2.x + r2.y;
        float mf = ((si - d1s)      < DELTA_) ? 1.f : 0.f;
        float mb = ((ssh[jj] - d2s) < DELTA_) ? 1.f : 0.f;
        deg += mf; ind += mb;
        u64 mf2 = pack2(mf, mf);
        u64 mb2 = pack2(mb, mb);
        const u64* xj2 = (const u64*)(xsh + jj*T_);
#pragma unroll
        for (int t = 0; t < 6; t++) {
            u64 xv = xj2[t];
            accf2[t] = fma2(mf2, xv, accf2[t]);
            accb2[t] = fma2(mb2, xv, accb2[t]);
        }
    }

    atomicAdd(&g_deg[bN + i], deg);
    atomicAdd(&g_ind[bN + i], ind);
    size_t obase = (size_t)(bN + i) * T_;
#pragma unroll
    for (int t = 0; t < 6; t++) {
        float2 f = unpack2(accf2[t]);
        float2 g = unpack2(accb2[t]);
        atomicAdd(&g_af[obase + 2*t    ], f.x);
        atomicAdd(&g_af[obase + 2*t + 1], f.y);
        atomicAdd(&g_ab[obase + 2*t    ], g.x);
        atomicAdd(&g_ab[obase + 2*t + 1], g.y);
    }
}

// ---------------- K3: fused gfin + buildz: z = relu(x*W1 + msg*W2), bf16 hi/lo ----------------
// block = 384 threads = 2 rows x 192 float4-columns; no div/mod on the hot path.
__global__ void __launch_bounds__(384) k_buildz(const float* __restrict__ x,
                                                const float* __restrict__ W1,
                                                const float* __restrict__ W2) {
    __shared__ float w1s[H_], w2s[H_];
    const int tid = threadIdx.x;
    if (tid < H_)            w1s[tid]      = W1[tid];
    else if (tid < 2*H_)     w2s[tid-H_]   = W2[tid-H_];
    __syncthreads();

    const int half = tid / 192;
    const int c    = tid % 192;
    const int row  = blockIdx.x * 2 + half;
    const int t    = c >> 4;
    const int h4   = (c & 15) * 4;
    const int b = row / N_, n = row % N_;

    float rf = (KHOPS_ * ALPHA_)       * __frcp_rn(fmaxf(g_deg[row], DEG_MIN_));
    float rb = (KHOPS_ * (1.f-ALPHA_)) * __frcp_rn(fmaxf(g_ind[row], DEG_MIN_));
    float gg = rf * g_af[row*T_ + t] + rb * g_ab[row*T_ + t];
    float xv = x[((size_t)(b*T_ + t))*N_ + n];

    float4 w1 = *(const float4*)&w1s[h4];
    float4 w2 = *(const float4*)&w2s[h4];
    float v0 = fmaxf(fmaf(xv, w1.x, gg * w2.x), 0.f);
    float v1 = fmaxf(fmaf(xv, w1.y, gg * w2.y), 0.f);
    float v2 = fmaxf(fmaf(xv, w1.z, gg * w2.z), 0.f);
    float v3 = fmaxf(fmaf(xv, w1.w, gg * w2.w), 0.f);
    __nv_bfloat16 h0, h1, h2, h3, l0, l1, l2, l3;
    split_bf16(v0, h0, l0); split_bf16(v1, h1, l1);
    split_bf16(v2, h2, l2); split_bf16(v3, h3, l3);
    size_t o = (size_t)row * TH_ + t*64 + h4;
    *(__nv_bfloat162*)&g_zh[o]   = __nv_bfloat162{h0, h1};
    *(__nv_bfloat162*)&g_zh[o+2] = __nv_bfloat162{h2, h3};
    *(__nv_bfloat162*)&g_zl[o]   = __nv_bfloat162{l0, l1};
    *(__nv_bfloat162*)&g_zl[o+2] = __nv_bfloat162{l2, l3};
}

// ---------------- K3b: all weight transposes + splits in one launch ----------------
__global__ void __launch_bounds__(256) k_prepall(
    const float* __restrict__ w1, const float* __restrict__ proj,
    const float* __restrict__ w2, const float* __restrict__ w3,
    const float* __restrict__ dw1, const float* __restrict__ dw2)
{
    int idx = blockIdx.x * 256 + threadIdx.x;
    if (idx < (HID2_+H_)*TH_) {
        int n = idx / TH_, k = idx % TH_;
        float v = (n < HID2_) ? w1[(size_t)k*HID2_ + n] : proj[(size_t)k*H_ + (n - HID2_)];
        __nv_bfloat16 h, l;
        split_bf16(v, h, l);
        g_wh[idx] = h;
        g_wl[idx] = l;
        return;
    }
    int c = idx - (HID2_+H_)*TH_;
    if (c >= 49152) return;
    float v;
    if (c < 16384)      { int j = c;         int n = j/128, k = j%128; v = w2 [(size_t)k*HID2_ + n]; }
    else if (c < 24576) { int j = c - 16384; int n = j/128, k = j%128; v = w3 [(size_t)k*H_    + n]; }
    else if (c < 32768) { int j = c - 24576; int n = j/64,  k = j%64;  v = dw1[(size_t)k*HID2_ + n]; }
    else                { int j = c - 32768; int n = j/128, k = j%128; v = dw2[(size_t)k*HID2_ + n]; }
    __nv_bfloat16 h, l;
    split_bf16(v, h, l);
    g_cwh[c] = h;
    g_cwl[c] = l;
}

// ---------------- K4: bf16x3 ldmatrix fused GEMM: h1(hi/lo)=relu(Z@w1+b1), zp=Z@proj ----------------
__global__ void __launch_bounds__(256) k_pair_mma(const float* __restrict__ b1v) {
    __shared__ __align__(16) __nv_bfloat16 Ah[128*KPCH];
    __shared__ __align__(16) __nv_bfloat16 Al[128*KPCH];
    __shared__ __align__(16) __nv_bfloat16 Bh[64*KPCH];
    __shared__ __align__(16) __nv_bfloat16 Bl[64*KPCH];

    const int tid  = threadIdx.x;
    const int w    = tid >> 5, lane = tid & 31;
    const int m0   = blockIdx.x * 128;
    const int n0   = blockIdx.y * 64;

    float acc[8][4];
#pragma unroll
    for (int t = 0; t < 8; t++)
#pragma unroll
        for (int j = 0; j < 4; j++) acc[t][j] = 0.f;

    const uint32_t aAh = s2u(Ah), aAl = s2u(Al), aBh = s2u(Bh), aBl = s2u(Bl);
    const int laneA_off = ((w*16 + (lane & 15))*KPCH)*2 + ((lane>>4)&1)*16;
    const int laneB_off = (((lane & 7) + ((lane>>4)&1)*8)*KPCH)*2 + ((lane>>3)&1)*16;

    for (int k0 = 0; k0 < TH_; k0 += 32) {
#pragma unroll
        for (int q = 0; q < 8; q++) {
            int idx = q*256 + tid;
            int r = idx >> 4, c = (idx & 15) * 2;
            *(uint32_t*)&Ah[r*KPCH + c] = *(const uint32_t*)&g_zh[(size_t)(m0+r)*TH_ + k0 + c];
            *(uint32_t*)&Al[r*KPCH + c] = *(const uint32_t*)&g_zl[(size_t)(m0+r)*TH_ + k0 + c];
        }
#pragma unroll
        for (int q = 0; q < 4; q++) {
            int idx = q*256 + tid;
            int r = idx >> 4, c = (idx & 15) * 2;
            *(uint32_t*)&Bh[r*KPCH + c] = *(const uint32_t*)&g_wh[(size_t)(n0+r)*TH_ + k0 + c];
            *(uint32_t*)&Bl[r*KPCH + c] = *(const uint32_t*)&g_wl[(size_t)(n0+r)*TH_ + k0 + c];
        }
        __syncthreads();
        mma_tile(acc, aAh, aAl, aBh, aBl, laneA_off, laneB_off);
        __syncthreads();
    }

    const int m  = m0 + w*16 + (lane >> 2);
    const int cl = (lane & 3) * 2;
    if (n0 < HID2_) {
#pragma unroll
        for (int t = 0; t < 8; t++) {
            int col = n0 + t*8 + cl;
            float b0 = __ldg(&b1v[col]), b1 = __ldg(&b1v[col+1]);
            float v00 = fmaxf(acc[t][0] + b0, 0.f), v01 = fmaxf(acc[t][1] + b1, 0.f);
            float v10 = fmaxf(acc[t][2] + b0, 0.f), v11 = fmaxf(acc[t][3] + b1, 0.f);
            __nv_bfloat16 h0,h1,h2,h3,l0,l1,l2,l3;
            split_bf16(v00,h0,l0); split_bf16(v01,h1,l1);
            split_bf16(v10,h2,l2); split_bf16(v11,h3,l3);
            *(__nv_bfloat162*)&g_h1h[(size_t)m*HID2_ + col]     = __nv_bfloat162{h0,h1};
            *(__nv_bfloat162*)&g_h1l[(size_t)m*HID2_ + col]     = __nv_bfloat162{l0,l1};
            *(__nv_bfloat162*)&g_h1h[(size_t)(m+8)*HID2_ + col] = __nv_bfloat162{h2,h3};
            *(__nv_bfloat162*)&g_h1l[(size_t)(m+8)*HID2_ + col] = __nv_bfloat162{l2,l3};
        }
    } else {
#pragma unroll
        for (int t = 0; t < 8; t++) {
            int col = t*8 + cl;
            *(float2*)&g_zp[(size_t)m*H_ + col]     = make_float2(acc[t][0], acc[t][1]);
            *(float2*)&g_zp[(size_t)(m+8)*H_ + col] = make_float2(acc[t][2], acc[t][3]);
        }
    }
}

// ---------------- K5: generic bf16x3 ldmatrix chain GEMM ----------------
template<int KD, bool RELU, bool HASAUX, bool DOBN, bool OUTF32, bool OUTHILO>
__global__ void __launch_bounds__(256) k_mma(
    const __nv_bfloat16* __restrict__ Ahp, const __nv_bfloat16* __restrict__ Alp,
    const __nv_bfloat16* __restrict__ Bhp, const __nv_bfloat16* __restrict__ Blp,
    const float* __restrict__ bias,
    const float* __restrict__ aux, int auxN,
    const float* __restrict__ bng, const float* __restrict__ bnb,
    const float* __restrict__ bnm, const float* __restrict__ bnv,
    float* __restrict__ oF, int oFN,
    __nv_bfloat16* __restrict__ oH, __nv_bfloat16* __restrict__ oL, int oN)
{
    __shared__ __align__(16) __nv_bfloat16 Ah[128*KPCH];
    __shared__ __align__(16) __nv_bfloat16 Al[128*KPCH];
    __shared__ __align__(16) __nv_bfloat16 Bh[64*KPCH];
    __shared__ __align__(16) __nv_bfloat16 Bl[64*KPCH];

    const int tid  = threadIdx.x;
    const int w    = tid >> 5, lane = tid & 31;
    const int m0   = blockIdx.x * 128;
    const int n0   = blockIdx.y * 64;

    float acc[8][4];
#pragma unroll
    for (int t = 0; t < 8; t++)
#pragma unroll
        for (int j = 0; j < 4; j++) acc[t][j] = 0.f;

    const uint32_t aAh = s2u(Ah), aAl = s2u(Al), aBh = s2u(Bh), aBl = s2u(Bl);
    const int laneA_off = ((w*16 + (lane & 15))*KPCH)*2 + ((lane>>4)&1)*16;
    const int laneB_off = (((lane & 7) + ((lane>>4)&1)*8)*KPCH)*2 + ((lane>>3)&1)*16;

#pragma unroll
    for (int k0 = 0; k0 < KD; k0 += 32) {
#pragma unroll
        for (int q = 0; q < 8; q++) {
            int idx = q*256 + tid;
            int r = idx >> 4, c = (idx & 15) * 2;
            *(uint32_t*)&Ah[r*KPCH + c] = *(const uint32_t*)&Ahp[(size_t)(m0+r)*KD + k0 + c];
            *(uint32_t*)&Al[r*KPCH + c] = *(const uint32_t*)&Alp[(size_t)(m0+r)*KD + k0 + c];
        }
#pragma unroll
        for (int q = 0; q < 4; q++) {
            int idx = q*256 + tid;
            int r = idx >> 4, c = (idx & 15) * 2;
            *(uint32_t*)&Bh[r*KPCH + c] = *(const uint32_t*)&Bhp[(size_t)(n0+r)*KD + k0 + c];
            *(uint32_t*)&Bl[r*KPCH + c] = *(const uint32_t*)&Blp[(size_t)(n0+r)*KD + k0 + c];
        }
        __syncthreads();
        mma_tile(acc, aAh, aAl, aBh, aBl, laneA_off, laneB_off);
        __syncthreads();
    }

    const int m  = m0 + w*16 + (lane >> 2);
    const int cl = (lane & 3) * 2;
#pragma unroll
    for (int t = 0; t < 8; t++) {
        int col = n0 + t*8 + cl;
        float b0 = __ldg(&bias[col]), b1 = __ldg(&bias[col+1]);
        float v[4] = { acc[t][0] + b0, acc[t][1] + b1, acc[t][2] + b0, acc[t][3] + b1 };
        if (HASAUX) {
            v[0] += aux[(size_t)m*auxN + col];
            v[1] += aux[(size_t)m*auxN + col + 1];
            v[2] += aux[(size_t)(m+8)*auxN + col];
            v[3] += aux[(size_t)(m+8)*auxN + col + 1];
        }
        if (DOBN) {
            float s0 = rsqrtf(__ldg(&bnv[col])   + BN_EPS_) * __ldg(&bng[col]);
            float s1 = rsqrtf(__ldg(&bnv[col+1]) + BN_EPS_) * __ldg(&bng[col+1]);
            float m0v = __ldg(&bnm[col]), m1v = __ldg(&bnm[col+1]);
            float a0 = __ldg(&bnb[col]),  a1 = __ldg(&bnb[col+1]);
            v[0] = (v[0] - m0v) * s0 + a0;
            v[1] = (v[1] - m1v) * s1 + a1;
            v[2] = (v[2] - m0v) * s0 + a0;
            v[3] = (v[3] - m1v) * s1 + a1;
        }
        if (RELU) {
#pragma unroll
            for (int q = 0; q < 4; q++) v[q] = fmaxf(v[q], 0.f);
        }
        if (OUTF32) {
            *(float2*)&oF[(size_t)m*oFN + col]     = make_float2(v[0], v[1]);
            *(float2*)&oF[(size_t)(m+8)*oFN + col] = make_float2(v[2], v[3]);
        }
        if (OUTHILO) {
            __nv_bfloat16 h0,h1,h2,h3,l0,l1,l2,l3;
            split_bf16(v[0],h0,l0); split_bf16(v[1],h1,l1);
            split_bf16(v[2],h2,l2); split_bf16(v[3],h3,l3);
            *(__nv_bfloat162*)&oH[(size_t)m*oN + col]     = __nv_bfloat162{h0,h1};
            *(__nv_bfloat162*)&oL[(size_t)m*oN + col]     = __nv_bfloat162{l0,l1};
            *(__nv_bfloat162*)&oH[(size_t)(m+8)*oN + col] = __nv_bfloat162{h2,h3};
            *(__nv_bfloat162*)&oL[(size_t)(m+8)*oN + col] = __nv_bfloat162{l2,l3};
        }
    }
}

// ---------------- K7: final stage, N=12, fused dual-GEMM + BN + transpose ----------------
__global__ void __launch_bounds__(64) k_final(
    const float* __restrict__ w3,  const float* __restrict__ b3,
    const float* __restrict__ pj,
    const float* __restrict__ bng, const float* __restrict__ bnb,
    const float* __restrict__ bnm, const float* __restrict__ bnv,
    float* __restrict__ out)
{
    __shared__ float w3s[HID2_*TOUT_];
    __shared__ float pjs[H_*TOUT_];
    const int tid = threadIdx.x;
    for (int idx = tid; idx < HID2_*TOUT_; idx += 64) w3s[idx] = w3[idx];
    for (int idx = tid; idx < H_*TOUT_;    idx += 64) pjs[idx] = pj[idx];
    __syncthreads();

    const int row = blockIdx.x * 64 + tid;
    float acc[TOUT_];
#pragma unroll
    for (int o = 0; o < TOUT_; o++) acc[o] = b3[o];

    const float4* hr = (const float4*)&g_h4[(size_t)row * HID2_];
#pragma unroll 4
    for (int k4 = 0; k4 < HID2_/4; k4++) {
        float4 hv = __ldg(&hr[k4]);
        float h[4] = {hv.x, hv.y, hv.z, hv.w};
#pragma unroll
        for (int q = 0; q < 4; q++) {
            int k = k4*4 + q;
#pragma unroll
            for (int o = 0; o < TOUT_; o++)
                acc[o] = fmaf(h[q], w3s[k*TOUT_ + o], acc[o]);
        }
    }
    const float4* er = (const float4*)&g_e[(size_t)row * H_];
#pragma unroll 4
    for (int k4 = 0; k4 < H_/4; k4++) {
        float4 ev = __ldg(&er[k4]);
        float e4[4] = {ev.x, ev.y, ev.z, ev.w};
#pragma unroll
        for (int q = 0; q < 4; q++) {
            int k = k4*4 + q;
#pragma unroll
            for (int o = 0; o < TOUT_; o++)
                acc[o] = fmaf(e4[q], pjs[k*TOUT_ + o], acc[o]);
        }
    }

    const int b = row / N_, n = row % N_;
#pragma unroll
    for (int o = 0; o < TOUT_; o++) {
        float c = (acc[o] - bnm[o]) * rsqrtf(bnv[o] + BN_EPS_) * bng[o] + bnb[o];
        out[((size_t)(b*TOUT_ + o))*N_ + n] = c;
    }
}

// ---------------- host launch ----------------
extern "C" void kernel_launch(void* const* d_in, const int* in_sizes, int n_in,
                              void* d_out, int out_size)
{
    const float* x        = (const float*)d_in[0];
    const float* W1       = (const float*)d_in[1];
    const float* W2       = (const float*)d_in[2];
    const float* enc_w1   = (const float*)d_in[3];
    const float* enc_b1   = (const float*)d_in[4];
    const float* enc_w2   = (const float*)d_in[5];
    const float* enc_b2   = (const float*)d_in[6];
    const float* enc_w3   = (const float*)d_in[7];
    const float* enc_b3   = (const float*)d_in[8];
    const float* enc_proj = (const float*)d_in[9];
    const float* enc_bn_g = (const float*)d_in[10];
    const float* enc_bn_b = (const float*)d_in[11];
    const float* enc_bn_m = (const float*)d_in[12];
    const float* enc_bn_v = (const float*)d_in[13];
    const float* dec_w1   = (const float*)d_in[14];
    const float* dec_b1   = (const float*)d_in[15];
    const float* dec_w2   = (const float*)d_in[16];
    const float* dec_b2   = (const float*)d_in[17];
    const float* dec_w3   = (const float*)d_in[18];
    const float* dec_b3   = (const float*)d_in[19];
    const float* dec_proj = (const float*)d_in[20];
    const float* dec_bn_g = (const float*)d_in[21];
    const float* dec_bn_b = (const float*)d_in[22];
    const float* dec_bn_m = (const float*)d_in[23];
    const float* dec_bn_v = (const float*)d_in[24];
    float* out = (float*)d_out;

    void *pzp, *pe, *ph4, *ph1h, *ph1l, *ph2h, *ph2l, *peh, *pel, *ph3h, *ph3l, *pcwh, *pcwl;
    cudaGetSymbolAddress(&pzp,  g_zp);
    cudaGetSymbolAddress(&pe,   g_e);
    cudaGetSymbolAddress(&ph4,  g_h4);
    cudaGetSymbolAddress(&ph1h, g_h1h);
    cudaGetSymbolAddress(&ph1l, g_h1l);
    cudaGetSymbolAddress(&ph2h, g_h2h);
    cudaGetSymbolAddress(&ph2l, g_h2l);
    cudaGetSymbolAddress(&peh,  g_eh);
    cudaGetSymbolAddress(&pel,  g_el);
    cudaGetSymbolAddress(&ph3h, g_h3h);
    cudaGetSymbolAddress(&ph3l, g_h3l);
    cudaGetSymbolAddress(&pcwh, g_cwh);
    cudaGetSymbolAddress(&pcwl, g_cwl);
    float* ZP = (float*)pzp;
    float* E  = (float*)pe;
    float* H4 = (float*)ph4;
    __nv_bfloat16* H1h = (__nv_bfloat16*)ph1h;
    __nv_bfloat16* H1l = (__nv_bfloat16*)ph1l;
    __nv_bfloat16* H2h = (__nv_bfloat16*)ph2h;
    __nv_bfloat16* H2l = (__nv_bfloat16*)ph2l;
    __nv_bfloat16* Eh  = (__nv_bfloat16*)peh;
    __nv_bfloat16* El  = (__nv_bfloat16*)pel;
    __nv_bfloat16* H3h = (__nv_bfloat16*)ph3h;
    __nv_bfloat16* H3l = (__nv_bfloat16*)ph3l;
    __nv_bfloat16* CWh = (__nv_bfloat16*)pcwh;
    __nv_bfloat16* CWl = (__nv_bfloat16*)pcwl;

    k_prepall<<<((HID2_+H_)*TH_ + 49152 + 255)/256, 256>>>(
        enc_w1, enc_proj, enc_w2, enc_w3, dec_w1, dec_w2);
    k_softmax<<<M_/64, 64>>>(x);
    k_graph  <<<dim3(N_/128, N_/JC, B_), 128>>>(x);
    k_buildz <<<M_/2, 384>>>(x, W1, W2);

    // h1(hi/lo) = relu(z @ enc_w1 + b1), zp = z @ enc_proj
    k_pair_mma<<<dim3(M_/128, 3), 256>>>(enc_b1);

    // h2(hi/lo) = relu(h1 @ enc_w2 + b2)   K=128, N=128
    k_mma<128,true ,false,false,false,true><<<dim3(M_/128, 2), 256>>>(
        H1h, H1l, CWh, CWl, enc_b2,
        nullptr, 0, nullptr, nullptr, nullptr, nullptr,
        nullptr, 0, H2h, H2l, HID2_);

    // e = BN(h2 @ enc_w3 + b3 + zp)        K=128, N=64 -> fp32 + hi/lo
    k_mma<128,false,true ,true ,true ,true><<<dim3(M_/128, 1), 256>>>(
        H2h, H2l, CWh + 16384, CWl + 16384, enc_b3,
        ZP, H_, enc_bn_g, enc_bn_b, enc_bn_m, enc_bn_v,
        E, H_, Eh, El, H_);

    // h3(hi/lo) = relu(e @ dec_w1 + db1)   K=64, N=128
    k_mma< 64,true ,false,false,false,true><<<dim3(M_/128, 2), 256>>>(
        Eh, El, CWh + 24576, CWl + 24576, dec_b1,
        nullptr, 0, nullptr, nullptr, nullptr, nullptr,
        nullptr, 0, H3h, H3l, HID2_);

    // h4 = relu(h3 @ dec_w2 + db2)         K=128, N=128 -> fp32
    k_mma<128,true ,false,false,true ,false><<<dim3(M_/128, 2), 256>>>(
        H3h, H3l, CWh + 32768, CWl + 32768, dec_b2,
        nullptr, 0, nullptr, nullptr, nullptr, nullptr,
        H4, HID2_, nullptr, nullptr, HID2_);

    // out = transpose(BN(h4 @ dec_w3 + db3 + e @ dec_proj))
    k_final<<<M_/64, 64>>>(dec_w3, dec_b3, dec_proj,
                           dec_bn_g, dec_bn_b, dec_bn_m, dec_bn_v, out);
}

// round 8
// speedup vs baseline: 2.5302x; 1.0181x over previous
#include <cuda_runtime.h>
#include <cuda_bf16.h>
#include <math.h>
#include <stdint.h>

#define B_    8
#define T_    12
#define N_    1536
#define H_    64
#define TH_   768
#define HID2_ 128
#define TOUT_ 12
#define M_    (B_*N_)          // 12288
#define DELTA_   0.5f
#define ALPHA_   0.3f
#define KHOPS_   3.0f
#define KL_EPS_  1e-10f
#define BN_EPS_  1e-5f
#define DEG_MIN_ 1e-6f

typedef unsigned long long u64;

// ---------------- packed fp32x2 helpers (sm_103a FFMA2) ----------------
__device__ __forceinline__ u64 fma2(u64 a, u64 b, u64 c) {
    u64 d;
    asm("fma.rn.f32x2 %0, %1, %2, %3;" : "=l"(d) : "l"(a), "l"(b), "l"(c));
    return d;
}
__device__ __forceinline__ u64 pack2(float x, float y) {
    u64 d;
    asm("mov.b64 %0, {%1, %2};" : "=l"(d) : "f"(x), "f"(y));
    return d;
}
__device__ __forceinline__ float2 unpack2(u64 v) {
    float2 r;
    asm("mov.b64 {%0, %1}, %2;" : "=f"(r.x), "=f"(r.y) : "l"(v));
    return r;
}

// ---------------- warp mma.sync bf16 + ldmatrix ----------------
__device__ __forceinline__ void mma_bf16(float* c,
    uint32_t a0, uint32_t a1, uint32_t a2, uint32_t a3,
    uint32_t b0, uint32_t b1)
{
    asm volatile(
        "mma.sync.aligned.m16n8k16.row.col.f32.bf16.bf16.f32 "
        "{%0,%1,%2,%3}, {%4,%5,%6,%7}, {%8,%9}, {%0,%1,%2,%3};"
        : "+f"(c[0]), "+f"(c[1]), "+f"(c[2]), "+f"(c[3])
        : "r"(a0), "r"(a1), "r"(a2), "r"(a3), "r"(b0), "r"(b1));
}
__device__ __forceinline__ void ldsm_x4(uint32_t& r0, uint32_t& r1,
                                        uint32_t& r2, uint32_t& r3, uint32_t addr)
{
    asm volatile("ldmatrix.sync.aligned.m8n8.x4.shared.b16 {%0,%1,%2,%3}, [%4];"
        : "=r"(r0), "=r"(r1), "=r"(r2), "=r"(r3) : "r"(addr));
}
__device__ __forceinline__ uint32_t s2u(const void* p) {
    uint32_t a;
    asm("{ .reg .u64 t; cvta.to.shared.u64 t, %1; cvt.u32.u64 %0, t; }" : "=r"(a) : "l"(p));
    return a;
}
__device__ __forceinline__ void split_bf16(float v, __nv_bfloat16& h, __nv_bfloat16& l) {
    h = __float2bfloat16(v);
    l = __float2bfloat16(v - __bfloat162float(h));
}

#define KPCH 40   // smem pitch (bf16); 80B row stride -> conflict-free ldmatrix, 8B-aligned rows

// bf16x3 ldmatrix inner step over one 32-k smem tile (A 128 rows, B 64 rows)
__device__ __forceinline__ void mma_tile(float acc[8][4],
    uint32_t aAh, uint32_t aAl, uint32_t aBh, uint32_t aBl,
    int laneA_off, int laneB_off)
{
#pragma unroll
    for (int ks = 0; ks < 2; ks++) {
        uint32_t ah[4], al[4];
        ldsm_x4(ah[0],ah[1],ah[2],ah[3], aAh + laneA_off + ks*32);
        ldsm_x4(al[0],al[1],al[2],al[3], aAl + laneA_off + ks*32);
#pragma unroll
        for (int t2 = 0; t2 < 4; t2++) {
            uint32_t bh[4], bl[4];
            ldsm_x4(bh[0],bh[1],bh[2],bh[3], aBh + laneB_off + t2*(16*KPCH*2) + ks*32);
            ldsm_x4(bl[0],bl[1],bl[2],bl[3], aBl + laneB_off + t2*(16*KPCH*2) + ks*32);
            mma_bf16(acc[2*t2],   ah[0],ah[1],ah[2],ah[3], bh[0],bh[1]);
            mma_bf16(acc[2*t2],   ah[0],ah[1],ah[2],ah[3], bl[0],bl[1]);
            mma_bf16(acc[2*t2],   al[0],al[1],al[2],al[3], bh[0],bh[1]);
            mma_bf16(acc[2*t2+1], ah[0],ah[1],ah[2],ah[3], bh[2],bh[3]);
            mma_bf16(acc[2*t2+1], ah[0],ah[1],ah[2],ah[3], bl[2],bl[3]);
            mma_bf16(acc[2*t2+1], al[0],al[1],al[2],al[3], bh[2],bh[3]);
        }
    }
}

// 8B-vectorized fills: A 128 rows x 32 k, B 64 rows x 32 k (hi+lo)
__device__ __forceinline__ void fill_A(__nv_bfloat16* Ah, __nv_bfloat16* Al,
    const __nv_bfloat16* __restrict__ gh, const __nv_bfloat16* __restrict__ gl,
    int m0, int KD, int k0, int tid)
{
#pragma unroll
    for (int q = 0; q < 4; q++) {
        int idx = q*256 + tid;
        int r = idx >> 3, c = (idx & 7) * 4;
        *(uint2*)&Ah[r*KPCH + c] = *(const uint2*)&gh[(size_t)(m0+r)*KD + k0 + c];
        *(uint2*)&Al[r*KPCH + c] = *(const uint2*)&gl[(size_t)(m0+r)*KD + k0 + c];
    }
}
__device__ __forceinline__ void fill_B(__nv_bfloat16* Bh, __nv_bfloat16* Bl,
    const __nv_bfloat16* __restrict__ gh, const __nv_bfloat16* __restrict__ gl,
    int n0, int KD, int k0, int tid)
{
#pragma unroll
    for (int q = 0; q < 2; q++) {
        int idx = q*256 + tid;
        int r = idx >> 3, c = (idx & 7) * 4;
        *(uint2*)&Bh[r*KPCH + c] = *(const uint2*)&gh[(size_t)(n0+r)*KD + k0 + c];
        *(uint2*)&Bl[r*KPCH + c] = *(const uint2*)&gl[(size_t)(n0+r)*KD + k0 + c];
    }
}

// ---------------- device scratch ----------------
__device__ __align__(16) float g_p [M_*T_];
__device__ __align__(16) float g_lp[M_*T_];
__device__ float g_s  [M_];
__device__ float g_deg[M_];
__device__ float g_ind[M_];
__device__ __align__(16) float g_af[M_*T_];
__device__ __align__(16) float g_ab[M_*T_];
__device__ __align__(16) float g_gg[M_*T_];
__device__ __align__(16) __nv_bfloat16 g_zh[(size_t)M_*TH_];
__device__ __align__(16) __nv_bfloat16 g_zl[(size_t)M_*TH_];
__device__ __align__(16) __nv_bfloat16 g_wh[(size_t)(HID2_+H_)*TH_];
__device__ __align__(16) __nv_bfloat16 g_wl[(size_t)(HID2_+H_)*TH_];
// chain weights [n][k] bf16 hi/lo: enc_w2@0 | enc_w3@16384 | dec_w1@24576 | dec_w2@32768
__device__ __align__(16) __nv_bfloat16 g_cwh[49152];
__device__ __align__(16) __nv_bfloat16 g_cwl[49152];
__device__ __align__(16) __nv_bfloat16 g_h1h[(size_t)M_*HID2_];
__device__ __align__(16) __nv_bfloat16 g_h1l[(size_t)M_*HID2_];
__device__ __align__(16) __nv_bfloat16 g_h2h[(size_t)M_*HID2_];
__device__ __align__(16) __nv_bfloat16 g_h2l[(size_t)M_*HID2_];
__device__ __align__(16) __nv_bfloat16 g_eh [(size_t)M_*H_];
__device__ __align__(16) __nv_bfloat16 g_el [(size_t)M_*H_];
__device__ __align__(16) __nv_bfloat16 g_h3h[(size_t)M_*HID2_];
__device__ __align__(16) __nv_bfloat16 g_h3l[(size_t)M_*HID2_];
__device__ __align__(16) float g_zp[(size_t)M_*H_];
__device__ __align__(16) float g_e [(size_t)M_*H_];
__device__ __align__(16) float g_h4[(size_t)M_*HID2_];

// ---------------- K1: softmax / logp / s ----------------
__global__ void __launch_bounds__(128) k_softmax(const float* __restrict__ x) {
    int bn = blockIdx.x * 128 + threadIdx.x;
    if (bn >= M_) return;
    int b = bn / N_, n = bn % N_;
    float v[T_];
    float mx = -1e30f;
#pragma unroll
    for (int t = 0; t < T_; t++) {
        v[t] = x[((size_t)(b*T_ + t))*N_ + n];
        mx = fmaxf(mx, v[t]);
    }
    float sum = 0.f;
#pragma unroll
    for (int t = 0; t < T_; t++) { v[t] = expf(v[t] - mx); sum += v[t]; }
    float inv = 1.f / sum;
    float s = 0.f;
    size_t base = (size_t)bn * T_;
#pragma unroll
    for (int t = 0; t < T_; t++) {
        float p  = v[t] * inv;
        float lp = logf(p + KL_EPS_);
        g_p [base + t] = p;
        g_lp[base + t] = lp;
        g_af[base + t] = 0.f;
        g_ab[base + t] = 0.f;
        s = fmaf(p, lp, s);
    }
    g_s[bn] = s;
    g_deg[bn] = 0.f;
    g_ind[bn] = 0.f;
}

// ---------------- weight prep (two launches so k_graph is the profiled 4th launch) ----------------
__global__ void __launch_bounds__(256) k_prep_enc(const float* __restrict__ w1,
                                                  const float* __restrict__ proj) {
    int idx = blockIdx.x * 256 + threadIdx.x;
    if (idx >= (HID2_+H_)*TH_) return;
    int n = idx / TH_, k = idx % TH_;
    float v = (n < HID2_) ? w1[(size_t)k*HID2_ + n] : proj[(size_t)k*H_ + (n - HID2_)];
    __nv_bfloat16 h, l;
    split_bf16(v, h, l);
    g_wh[idx] = h;
    g_wl[idx] = l;
}
__global__ void __launch_bounds__(256) k_prep_chain(const float* __restrict__ w2,
                                                    const float* __restrict__ w3,
                                                    const float* __restrict__ dw1,
                                                    const float* __restrict__ dw2) {
    int c = blockIdx.x * 256 + threadIdx.x;
    if (c >= 49152) return;
    float v;
    if (c < 16384)      { int j = c;         int n = j/128, k = j%128; v = w2 [(size_t)k*HID2_ + n]; }
    else if (c < 24576) { int j = c - 16384; int n = j/128, k = j%128; v = w3 [(size_t)k*H_    + n]; }
    else if (c < 32768) { int j = c - 24576; int n = j/64,  k = j%64;  v = dw1[(size_t)k*HID2_ + n]; }
    else                { int j = c - 32768; int n = j/128, k = j%128; v = dw2[(size_t)k*HID2_ + n]; }
    __nv_bfloat16 h, l;
    split_bf16(v, h, l);
    g_cwh[c] = h;
    g_cwl[c] = l;
}

// ---------------- K2: graph threshold + masked aggregation (4th launch -> profiled) ----------------
#define JC 256
__global__ void __launch_bounds__(128) k_graph(const float* __restrict__ x) {
    __shared__ __align__(16) float psh[JC*T_];
    __shared__ __align__(16) float lsh[JC*T_];
    __shared__ __align__(16) float xsh[JC*T_];
    __shared__ float ssh[JC];

    const int tid = threadIdx.x;
    const int b   = blockIdx.z;
    const int i   = blockIdx.x * 128 + tid;
    const int j0  = blockIdx.y * JC;
    const int bN  = b * N_;

    {
        size_t base = (size_t)(bN + j0) * T_;
        const float4* sp = (const float4*)(g_p  + base);
        const float4* sl = (const float4*)(g_lp + base);
#pragma unroll
        for (int q = 0; q < (JC*T_/4)/128; q++) {
            int idx = q*128 + tid;
            ((float4*)psh)[idx] = sp[idx];
            ((float4*)lsh)[idx] = sl[idx];
        }
#pragma unroll
        for (int t = 0; t < T_; t++) {
            xsh[tid*T_ + t]        = x[((size_t)(b*T_ + t))*N_ + j0 + tid];
            xsh[(tid+128)*T_ + t]  = x[((size_t)(b*T_ + t))*N_ + j0 + tid + 128];
        }
        ssh[tid]       = g_s[bN + j0 + tid];
        ssh[tid + 128] = g_s[bN + j0 + tid + 128];
    }

    u64 pi2[6], li2[6];
    {
        const ulonglong2* pp = (const ulonglong2*)(g_p  + (size_t)(bN + i)*T_);
        const ulonglong2* lp = (const ulonglong2*)(g_lp + (size_t)(bN + i)*T_);
#pragma unroll
        for (int q = 0; q < 3; q++) {
            ulonglong2 a = pp[q]; pi2[2*q] = a.x; pi2[2*q+1] = a.y;
            ulonglong2 c = lp[q]; li2[2*q] = c.x; li2[2*q+1] = c.y;
        }
    }
    const float si = g_s[bN + i];

    u64 accf2[6], accb2[6];
#pragma unroll
    for (int t = 0; t < 6; t++) { accf2[t] = 0ull; accb2[t] = 0ull; }
    float deg = 0.f, ind = 0.f;

    __syncthreads();

    for (int jj = 0; jj < JC; jj++) {
        const u64* pj2 = (const u64*)(psh + jj*T_);
        const u64* lj2 = (const u64*)(lsh + jj*T_);
        u64 d1 = 0ull, d2 = 0ull;
#pragma unroll
        for (int t = 0; t < 6; t++) {
            d1 = fma2(pi2[t], lj2[t], d1);
            d2 = fma2(pj2[t], li2[t], d2);
        }
        float2 r1 = unpack2(d1);
        float2 r2 = unpack2(d2);
        float d1s = r1.x + r1.y;
        float d2s = r2.x + r2.y;
        float mf = ((si - d1s)      < DELTA_) ? 1.f : 0.f;
        float mb = ((ssh[jj] - d2s) < DELTA_) ? 1.f : 0.f;
        deg += mf; ind += mb;
        u64 mf2 = pack2(mf, mf);
        u64 mb2 = pack2(mb, mb);
        const u64* xj2 = (const u64*)(xsh + jj*T_);
#pragma unroll
        for (int t = 0; t < 6; t++) {
            u64 xv = xj2[t];
            accf2[t] = fma2(mf2, xv, accf2[t]);
            accb2[t] = fma2(mb2, xv, accb2[t]);
        }
    }

    atomicAdd(&g_deg[bN + i], deg);
    atomicAdd(&g_ind[bN + i], ind);
    size_t obase = (size_t)(bN + i) * T_;
#pragma unroll
    for (int t = 0; t < 6; t++) {
        float2 f = unpack2(accf2[t]);
        float2 g = unpack2(accb2[t]);
        atomicAdd(&g_af[obase + 2*t    ], f.x);
        atomicAdd(&g_af[obase + 2*t + 1], f.y);
        atomicAdd(&g_ab[obase + 2*t    ], g.x);
        atomicAdd(&g_ab[obase + 2*t + 1], g.y);
    }
}

// ---------------- K2b: finalize message ----------------
__global__ void k_gfin() {
    int row = blockIdx.x * 128 + threadIdx.x;
    if (row >= M_) return;
    float rf = (KHOPS_ * ALPHA_)        * __frcp_rn(fmaxf(g_deg[row], DEG_MIN_));
    float rb = (KHOPS_ * (1.f-ALPHA_))  * __frcp_rn(fmaxf(g_ind[row], DEG_MIN_));
    size_t base = (size_t)row * T_;
#pragma unroll
    for (int t = 0; t < T_; t++)
        g_gg[base + t] = rf * g_af[base + t] + rb * g_ab[base + t];
}

// ---------------- K3: build z = relu(x*W1 + g*W2), bf16 hi/lo (round-6 proven layout) ----------------
__global__ void __launch_bounds__(256) k_buildz(const float* __restrict__ x,
                                                const float* __restrict__ W1,
                                                const float* __restrict__ W2) {
    int idx4 = blockIdx.x * 256 + threadIdx.x;
    if (idx4 >= M_*TH_/4) return;
    int row = idx4 / (TH_/4);
    int c4  = idx4 % (TH_/4);
    int t   = c4 >> 4;
    int h4  = (c4 & 15) * 4;
    int b = row / N_, n = row % N_;
    float xv = x[((size_t)(b*T_ + t))*N_ + n];
    float gg = g_gg[row*T_ + t];
    float4 w1 = *(const float4*)&W1[h4];
    float4 w2 = *(const float4*)&W2[h4];
    float v0 = fmaxf(fmaf(xv, w1.x, gg * w2.x), 0.f);
    float v1 = fmaxf(fmaf(xv, w1.y, gg * w2.y), 0.f);
    float v2 = fmaxf(fmaf(xv, w1.z, gg * w2.z), 0.f);
    float v3 = fmaxf(fmaf(xv, w1.w, gg * w2.w), 0.f);
    __nv_bfloat16 h0, h1, h2, h3, l0, l1, l2, l3;
    split_bf16(v0, h0, l0); split_bf16(v1, h1, l1);
    split_bf16(v2, h2, l2); split_bf16(v3, h3, l3);
    size_t o = (size_t)idx4 * 4;
    *(__nv_bfloat162*)&g_zh[o]   = __nv_bfloat162{h0, h1};
    *(__nv_bfloat162*)&g_zh[o+2] = __nv_bfloat162{h2, h3};
    *(__nv_bfloat162*)&g_zl[o]   = __nv_bfloat162{l0, l1};
    *(__nv_bfloat162*)&g_zl[o+2] = __nv_bfloat162{l2, l3};
}

// ---------------- K4: bf16x3 ldmatrix fused GEMM: h1(hi/lo)=relu(Z@w1+b1), zp=Z@proj ----------------
__global__ void __launch_bounds__(256) k_pair_mma(const float* __restrict__ b1v) {
    __shared__ __align__(16) __nv_bfloat16 Ah[128*KPCH];
    __shared__ __align__(16) __nv_bfloat16 Al[128*KPCH];
    __shared__ __align__(16) __nv_bfloat16 Bh[64*KPCH];
    __shared__ __align__(16) __nv_bfloat16 Bl[64*KPCH];

    const int tid  = threadIdx.x;
    const int w    = tid >> 5, lane = tid & 31;
    const int m0   = blockIdx.x * 128;
    const int n0   = blockIdx.y * 64;

    float acc[8][4];
#pragma unroll
    for (int t = 0; t < 8; t++)
#pragma unroll
        for (int j = 0; j < 4; j++) acc[t][j] = 0.f;

    const uint32_t aAh = s2u(Ah), aAl = s2u(Al), aBh = s2u(Bh), aBl = s2u(Bl);
    const int laneA_off = ((w*16 + (lane & 15))*KPCH)*2 + ((lane>>4)&1)*16;
    const int laneB_off = (((lane & 7) + ((lane>>4)&1)*8)*KPCH)*2 + ((lane>>3)&1)*16;

    for (int k0 = 0; k0 < TH_; k0 += 32) {
        fill_A(Ah, Al, g_zh, g_zl, m0, TH_, k0, tid);
        fill_B(Bh, Bl, g_wh, g_wl, n0, TH_, k0, tid);
        __syncthreads();
        mma_tile(acc, aAh, aAl, aBh, aBl, laneA_off, laneB_off);
        __syncthreads();
    }

    const int m  = m0 + w*16 + (lane >> 2);
    const int cl = (lane & 3) * 2;
    if (n0 < HID2_) {
#pragma unroll
        for (int t = 0; t < 8; t++) {
            int col = n0 + t*8 + cl;
            float b0 = __ldg(&b1v[col]), b1 = __ldg(&b1v[col+1]);
            float v00 = fmaxf(acc[t][0] + b0, 0.f), v01 = fmaxf(acc[t][1] + b1, 0.f);
            float v10 = fmaxf(acc[t][2] + b0, 0.f), v11 = fmaxf(acc[t][3] + b1, 0.f);
            __nv_bfloat16 h0,h1,h2,h3,l0,l1,l2,l3;
            split_bf16(v00,h0,l0); split_bf16(v01,h1,l1);
            split_bf16(v10,h2,l2); split_bf16(v11,h3,l3);
            *(__nv_bfloat162*)&g_h1h[(size_t)m*HID2_ + col]     = __nv_bfloat162{h0,h1};
            *(__nv_bfloat162*)&g_h1l[(size_t)m*HID2_ + col]     = __nv_bfloat162{l0,l1};
            *(__nv_bfloat162*)&g_h1h[(size_t)(m+8)*HID2_ + col] = __nv_bfloat162{h2,h3};
            *(__nv_bfloat162*)&g_h1l[(size_t)(m+8)*HID2_ + col] = __nv_bfloat162{l2,l3};
        }
    } else {
#pragma unroll
        for (int t = 0; t < 8; t++) {
            int col = t*8 + cl;
            *(float2*)&g_zp[(size_t)m*H_ + col]     = make_float2(acc[t][0], acc[t][1]);
            *(float2*)&g_zp[(size_t)(m+8)*H_ + col] = make_float2(acc[t][2], acc[t][3]);
        }
    }
}

// ---------------- K5: generic bf16x3 ldmatrix chain GEMM ----------------
template<int KD, bool RELU, bool HASAUX, bool DOBN, bool OUTF32, bool OUTHILO>
__global__ void __launch_bounds__(256) k_mma(
    const __nv_bfloat16* __restrict__ Ahp, const __nv_bfloat16* __restrict__ Alp,
    const __nv_bfloat16* __restrict__ Bhp, const __nv_bfloat16* __restrict__ Blp,
    const float* __restrict__ bias,
    const float* __restrict__ aux, int auxN,
    const float* __restrict__ bng, const float* __restrict__ bnb,
    const float* __restrict__ bnm, const float* __restrict__ bnv,
    float* __restrict__ oF, int oFN,
    __nv_bfloat16* __restrict__ oH, __nv_bfloat16* __restrict__ oL, int oN)
{
    __shared__ __align__(16) __nv_bfloat16 Ah[128*KPCH];
    __shared__ __align__(16) __nv_bfloat16 Al[128*KPCH];
    __shared__ __align__(16) __nv_bfloat16 Bh[64*KPCH];
    __shared__ __align__(16) __nv_bfloat16 Bl[64*KPCH];

    const int tid  = threadIdx.x;
    const int w    = tid >> 5, lane = tid & 31;
    const int m0   = blockIdx.x * 128;
    const int n0   = blockIdx.y * 64;

    float acc[8][4];
#pragma unroll
    for (int t = 0; t < 8; t++)
#pragma unroll
        for (int j = 0; j < 4; j++) acc[t][j] = 0.f;

    const uint32_t aAh = s2u(Ah), aAl = s2u(Al), aBh = s2u(Bh), aBl = s2u(Bl);
    const int laneA_off = ((w*16 + (lane & 15))*KPCH)*2 + ((lane>>4)&1)*16;
    const int laneB_off = (((lane & 7) + ((lane>>4)&1)*8)*KPCH)*2 + ((lane>>3)&1)*16;

#pragma unroll
    for (int k0 = 0; k0 < KD; k0 += 32) {
        fill_A(Ah, Al, Ahp, Alp, m0, KD, k0, tid);
        fill_B(Bh, Bl, Bhp, Blp, n0, KD, k0, tid);
        __syncthreads();
        mma_tile(acc, aAh, aAl, aBh, aBl, laneA_off, laneB_off);
        __syncthreads();
    }

    const int m  = m0 + w*16 + (lane >> 2);
    const int cl = (lane & 3) * 2;
#pragma unroll
    for (int t = 0; t < 8; t++) {
        int col = n0 + t*8 + cl;
        float b0 = __ldg(&bias[col]), b1 = __ldg(&bias[col+1]);
        float v[4] = { acc[t][0] + b0, acc[t][1] + b1, acc[t][2] + b0, acc[t][3] + b1 };
        if (HASAUX) {
            v[0] += aux[(size_t)m*auxN + col];
            v[1] += aux[(size_t)m*auxN + col + 1];
            v[2] += aux[(size_t)(m+8)*auxN + col];
            v[3] += aux[(size_t)(m+8)*auxN + col + 1];
        }
        if (DOBN) {
            float s0 = rsqrtf(__ldg(&bnv[col])   + BN_EPS_) * __ldg(&bng[col]);
            float s1 = rsqrtf(__ldg(&bnv[col+1]) + BN_EPS_) * __ldg(&bng[col+1]);
            float m0v = __ldg(&bnm[col]), m1v = __ldg(&bnm[col+1]);
            float a0 = __ldg(&bnb[col]),  a1 = __ldg(&bnb[col+1]);
            v[0] = (v[0] - m0v) * s0 + a0;
            v[1] = (v[1] - m1v) * s1 + a1;
            v[2] = (v[2] - m0v) * s0 + a0;
            v[3] = (v[3] - m1v) * s1 + a1;
        }
        if (RELU) {
#pragma unroll
            for (int q = 0; q < 4; q++) v[q] = fmaxf(v[q], 0.f);
        }
        if (OUTF32) {
            *(float2*)&oF[(size_t)m*oFN + col]     = make_float2(v[0], v[1]);
            *(float2*)&oF[(size_t)(m+8)*oFN + col] = make_float2(v[2], v[3]);
        }
        if (OUTHILO) {
            __nv_bfloat16 h0,h1,h2,h3,l0,l1,l2,l3;
            split_bf16(v[0],h0,l0); split_bf16(v[1],h1,l1);
            split_bf16(v[2],h2,l2); split_bf16(v[3],h3,l3);
            *(__nv_bfloat162*)&oH[(size_t)m*oN + col]     = __nv_bfloat162{h0,h1};
            *(__nv_bfloat162*)&oL[(size_t)m*oN + col]     = __nv_bfloat162{l0,l1};
            *(__nv_bfloat162*)&oH[(size_t)(m+8)*oN + col] = __nv_bfloat162{h2,h3};
            *(__nv_bfloat162*)&oL[(size_t)(m+8)*oN + col] = __nv_bfloat162{l2,l3};
        }
    }
}

// ---------------- K7: final stage, column-split (2 threads/row, 6 outputs each) ----------------
__global__ void __launch_bounds__(128) k_final(
    const float* __restrict__ w3,  const float* __restrict__ b3,
    const float* __restrict__ pj,
    const float* __restrict__ bng, const float* __restrict__ bnb,
    const float* __restrict__ bnm, const float* __restrict__ bnv,
    float* __restrict__ out)
{
    __shared__ float w3s[HID2_*TOUT_];
    __shared__ float pjs[H_*TOUT_];
    const int tid = threadIdx.x;
    for (int idx = tid; idx < HID2_*TOUT_; idx += 128) w3s[idx] = w3[idx];
    for (int idx = tid; idx < H_*TOUT_;    idx += 128) pjs[idx] = pj[idx];
    __syncthreads();

    const int gid  = blockIdx.x * 128 + tid;
    const int row  = gid >> 1;
    const int ob   = (gid & 1) * 6;   // output column base (6 per thread)
    float acc[6];
#pragma unroll
    for (int o = 0; o < 6; o++) acc[o] = b3[ob + o];

    const float4* hr = (const float4*)&g_h4[(size_t)row * HID2_];
#pragma unroll 4
    for (int k4 = 0; k4 < HID2_/4; k4++) {
        float4 hv = __ldg(&hr[k4]);
        float h[4] = {hv.x, hv.y, hv.z, hv.w};
#pragma unroll
        for (int q = 0; q < 4; q++) {
            int k = k4*4 + q;
#pragma unroll
            for (int o = 0; o < 6; o++)
                acc[o] = fmaf(h[q], w3s[k*TOUT_ + ob + o], acc[o]);
        }
    }
    const float4* er = (const float4*)&g_e[(size_t)row * H_];
#pragma unroll 4
    for (int k4 = 0; k4 < H_/4; k4++) {
        float4 ev = __ldg(&er[k4]);
        float e4[4] = {ev.x, ev.y, ev.z, ev.w};
#pragma unroll
        for (int q = 0; q < 4; q++) {
            int k = k4*4 + q;
#pragma unroll
            for (int o = 0; o < 6; o++)
                acc[o] = fmaf(e4[q], pjs[k*TOUT_ + ob + o], acc[o]);
        }
    }

    const int b = row / N_, n = row % N_;
#pragma unroll
    for (int o = 0; o < 6; o++) {
        int oo = ob + o;
        float c = (acc[o] - bnm[oo]) * rsqrtf(bnv[oo] + BN_EPS_) * bng[oo] + bnb[oo];
        out[((size_t)(b*TOUT_ + oo))*N_ + n] = c;
    }
}

// ---------------- host launch ----------------
extern "C" void kernel_launch(void* const* d_in, const int* in_sizes, int n_in,
                              void* d_out, int out_size)
{
    const float* x        = (const float*)d_in[0];
    const float* W1       = (const float*)d_in[1];
    const float* W2       = (const float*)d_in[2];
    const float* enc_w1   = (const float*)d_in[3];
    const float* enc_b1   = (const float*)d_in[4];
    const float* enc_w2   = (const float*)d_in[5];
    const float* enc_b2   = (const float*)d_in[6];
    const float* enc_w3   = (const float*)d_in[7];
    const float* enc_b3   = (const float*)d_in[8];
    const float* enc_proj = (const float*)d_in[9];
    const float* enc_bn_g = (const float*)d_in[10];
    const float* enc_bn_b = (const float*)d_in[11];
    const float* enc_bn_m = (const float*)d_in[12];
    const float* enc_bn_v = (const float*)d_in[13];
    const float* dec_w1   = (const float*)d_in[14];
    const float* dec_b1   = (const float*)d_in[15];
    const float* dec_w2   = (const float*)d_in[16];
    const float* dec_b2   = (const float*)d_in[17];
    const float* dec_w3   = (const float*)d_in[18];
    const float* dec_b3   = (const float*)d_in[19];
    const float* dec_proj = (const float*)d_in[20];
    const float* dec_bn_g = (const float*)d_in[21];
    const float* dec_bn_b = (const float*)d_in[22];
    const float* dec_bn_m = (const float*)d_in[23];
    const float* dec_bn_v = (const float*)d_in[24];
    float* out = (float*)d_out;

    void *pzp, *pe, *ph4, *ph1h, *ph1l, *ph2h, *ph2l, *peh, *pel, *ph3h, *ph3l, *pcwh, *pcwl;
    cudaGetSymbolAddress(&pzp,  g_zp);
    cudaGetSymbolAddress(&pe,   g_e);
    cudaGetSymbolAddress(&ph4,  g_h4);
    cudaGetSymbolAddress(&ph1h, g_h1h);
    cudaGetSymbolAddress(&ph1l, g_h1l);
    cudaGetSymbolAddress(&ph2h, g_h2h);
    cudaGetSymbolAddress(&ph2l, g_h2l);
    cudaGetSymbolAddress(&peh,  g_eh);
    cudaGetSymbolAddress(&pel,  g_el);
    cudaGetSymbolAddress(&ph3h, g_h3h);
    cudaGetSymbolAddress(&ph3l, g_h3l);
    cudaGetSymbolAddress(&pcwh, g_cwh);
    cudaGetSymbolAddress(&pcwl, g_cwl);
    float* ZP = (float*)pzp;
    float* E  = (float*)pe;
    float* H4 = (float*)ph4;
    __nv_bfloat16* H1h = (__nv_bfloat16*)ph1h;
    __nv_bfloat16* H1l = (__nv_bfloat16*)ph1l;
    __nv_bfloat16* H2h = (__nv_bfloat16*)ph2h;
    __nv_bfloat16* H2l = (__nv_bfloat16*)ph2l;
    __nv_bfloat16* Eh  = (__nv_bfloat16*)peh;
    __nv_bfloat16* El  = (__nv_bfloat16*)pel;
    __nv_bfloat16* H3h = (__nv_bfloat16*)ph3h;
    __nv_bfloat16* H3l = (__nv_bfloat16*)ph3l;
    __nv_bfloat16* CWh = (__nv_bfloat16*)pcwh;
    __nv_bfloat16* CWl = (__nv_bfloat16*)pcwl;

    // launch order chosen so k_graph is the 4th launch (ncu capture slot)
    k_softmax  <<<M_/128, 128>>>(x);                                   // 1
    k_prep_enc <<<((HID2_+H_)*TH_ + 255)/256, 256>>>(enc_w1, enc_proj); // 2
    k_prep_chain<<<192, 256>>>(enc_w2, enc_w3, dec_w1, dec_w2);         // 3
    k_graph    <<<dim3(N_/128, N_/JC, B_), 128>>>(x);                   // 4  <- profiled
    k_gfin     <<<M_/128, 128>>>();                                     // 5
    k_buildz   <<<(M_*TH_/4)/256, 256>>>(x, W1, W2);                    // 6

    // h1(hi/lo) = relu(z @ enc_w1 + b1), zp = z @ enc_proj
    k_pair_mma<<<dim3(M_/128, 3), 256>>>(enc_b1);                       // 7

    // h2(hi/lo) = relu(h1 @ enc_w2 + b2)   K=128, N=128
    k_mma<128,true ,false,false,false,true><<<dim3(M_/128, 2), 256>>>(
        H1h, H1l, CWh, CWl, enc_b2,
        nullptr, 0, nullptr, nullptr, nullptr, nullptr,
        nullptr, 0, H2h, H2l, HID2_);

    // e = BN(h2 @ enc_w3 + b3 + zp)        K=128, N=64 -> fp32 + hi/lo
    k_mma<128,false,true ,true ,true ,true><<<dim3(M_/128, 1), 256>>>(
        H2h, H2l, CWh + 16384, CWl + 16384, enc_b3,
        ZP, H_, enc_bn_g, enc_bn_b, enc_bn_m, enc_bn_v,
        E, H_, Eh, El, H_);

    // h3(hi/lo) = relu(e @ dec_w1 + db1)   K=64, N=128
    k_mma< 64,true ,false,false,false,true><<<dim3(M_/128, 2), 256>>>(
        Eh, El, CWh + 24576, CWl + 24576, dec_b1,
        nullptr, 0, nullptr, nullptr, nullptr, nullptr,
        nullptr, 0, H3h, H3l, HID2_);

    // h4 = relu(h3 @ dec_w2 + db2)         K=128, N=128 -> fp32
    k_mma<128,true ,false,false,true ,false><<<dim3(M_/128, 2), 256>>>(
        H3h, H3l, CWh + 32768, CWl + 32768, dec_b2,
        nullptr, 0, nullptr, nullptr, nullptr, nullptr,
        H4, HID2_, nullptr, nullptr, HID2_);

    // out = transpose(BN(h4 @ dec_w3 + db3 + e @ dec_proj))
    k_final<<<M_/64, 128>>>(dec_w3, dec_b3, dec_proj,
                            dec_bn_g, dec_bn_b, dec_bn_m, dec_bn_v, out);
}